// round 12
// baseline (speedup 1.0000x reference)
#include <cuda_runtime.h>
#include <cuda_fp16.h>
#include <math.h>
#include <stdint.h>

#define BB 4
#define CC 1024
#define CI 512
#define TT 16
#define HH 28
#define WW 28
#define NQ 12544
#define NKr 3136
#define NKp 3328
#define BN_EPS 1e-5f

// ---------------- scratch ----------------
__device__ __align__(256) __half d_xt  [(size_t)BB*NQ*CC];
__device__ __align__(256) __half d_xpt [(size_t)BB*NKp*CC];
__device__ __align__(256) __half d_th  [(size_t)BB*NQ*CI];
__device__ __align__(256) __half d_ph  [(size_t)BB*NKp*CI];
__device__ __align__(256) __half d_g2  [(size_t)BB*CI*NKp];
__device__ __align__(256) __half d_f   [(size_t)BB*NQ*NKp];   // exp(logits)
__device__ __align__(256) __half d_y   [(size_t)BB*NQ*CI];
__device__ __align__(256) __half d_wy  [(size_t)BB*CC*NQ];
__device__ __align__(256) __half d_thw [CI*CC];
__device__ __align__(256) __half d_phw [CI*CC];
__device__ __align__(256) __half d_gw  [CI*CC];
__device__ __align__(256) __half d_ww  [CC*CI];
__device__ float d_rowsum[(size_t)BB*NQ];
__device__ float d_rowinv[(size_t)BB*NQ];
__device__ float d_bnsum[CC];
__device__ float d_bnsq [CC];
__device__ float d_mean[CC];
__device__ float d_istd[CC];

// ---------------- helpers ----------------
__device__ __forceinline__ uint32_t s2u(const void* p) {
    uint32_t a;
    asm("{ .reg .u64 t; cvta.to.shared.u64 t, %1; cvt.u32.u64 %0, t; }" : "=r"(a) : "l"(p));
    return a;
}
__device__ __forceinline__ void st2(float* p, float a, float b) {
    *(float2*)p = make_float2(a, b);
}
__device__ __forceinline__ void st2(__half* p, float a, float b) {
    *(__half2*)p = __floats2half2_rn(a, b);
}

// ---------------- fp16 mma.sync TN GEMM ----------------
// CTA 256x128, 512 threads (16 warps = 4m x 4n of 64x32), BK=64, NSTAGE=3.
// D[M,N] = scale * A[M,K] @ B[N,K]^T (+ biasM[m]) (+ biasN[n])
// M mult of 256, N mult of 128, K mult of 64. grid=(N/128, M/256, batch)
// Fused epilogues: rowSum (exp+rowsums), rowScale, bnSum/bnSq.
#define ROW_B    144                   // 128B data + 16B pad
#define TILE_A_B (256*ROW_B)           // 36864
#define TILE_B_B (128*ROW_B)           // 18432
#define STG_B    (TILE_A_B + TILE_B_B) // 55296
#define NSTAGE   3
#define GEMM_SMEM (NSTAGE*STG_B)       // 165888 -> 1 CTA/SM, 16 warps

template<typename TO>
__global__ __launch_bounds__(512, 1)
void gemm_tn(const __half* __restrict__ A, const __half* __restrict__ B,
             TO* __restrict__ D, int K, int lda, int ldb, int ldd,
             long long sA, long long sB, long long sD,
             const float* __restrict__ biasM, const float* __restrict__ biasN,
             float scale,
             float* __restrict__ rowSum, const float* __restrict__ rowScale,
             int nValid, long long sR,
             float* __restrict__ bnSum, float* __restrict__ bnSq)
{
    extern __shared__ char smem[];
    __shared__ float sm_r1[256];
    __shared__ float sm_r2[256];
    const uint32_t smem_b = s2u(smem);
    const int tid = threadIdx.x, wid = tid >> 5, lane = tid & 31;
    const int wm = wid >> 2, wn = wid & 3;        // 4m x 4n warps, tile 64x32
    const int g = lane >> 2, tg = lane & 3;
    const int m0 = blockIdx.y << 8, n0 = blockIdx.x << 7;
    A += (long long)blockIdx.z * sA + (size_t)m0 * lda;
    B += (long long)blockIdx.z * sB + (size_t)n0 * ldb;
    D += (long long)blockIdx.z * sD;
    if (rowSum)   rowSum   += (long long)blockIdx.z * sR;
    if (rowScale) rowScale += (long long)blockIdx.z * sR;
    const int ktiles = K >> 6;

    // producer: 384 rows x 8 chunks(16B) = 3072 chunks; 512 threads x 6
    const int pr = tid >> 3;                      // 0..63
    const int pc = tid & 7;

    const uint32_t aoff = (uint32_t)(wm * 64 + (lane & 15)) * ROW_B + ((lane >> 4) << 4);
    const uint32_t boff = (uint32_t)TILE_A_B
                        + (uint32_t)(wn * 32 + ((lane >> 4) << 3) + (lane & 7)) * ROW_B
                        + (((lane >> 3) & 1) << 4);

    float acc[4][4][4];
    #pragma unroll
    for (int i = 0; i < 4; i++)
        #pragma unroll
        for (int j = 0; j < 4; j++)
            #pragma unroll
            for (int q = 0; q < 4; q++) acc[i][j][q] = 0.0f;

    // prologue
    #pragma unroll
    for (int s = 0; s < NSTAGE - 1; s++) {
        const __half* Ab = A + (s << 6) + (pc << 3);
        const __half* Bb = B + (s << 6) + (pc << 3);
        uint32_t Sa = smem_b + s * STG_B + pc * 16;
        uint32_t Sb = Sa + TILE_A_B;
        #pragma unroll
        for (int l = 0; l < 4; l++) {
            const int r = pr + (l << 6);
            asm volatile("cp.async.cg.shared.global [%0], [%1], 16;"
                         :: "r"(Sa + r * ROW_B), "l"(Ab + (size_t)r * lda));
        }
        #pragma unroll
        for (int l = 0; l < 2; l++) {
            const int r = pr + (l << 6);
            asm volatile("cp.async.cg.shared.global [%0], [%1], 16;"
                         :: "r"(Sb + r * ROW_B), "l"(Bb + (size_t)r * ldb));
        }
        asm volatile("cp.async.commit_group;");
    }

    int sc = 0;
    for (int kt = 0; kt < ktiles; kt++) {
        asm volatile("cp.async.wait_group %0;" :: "n"(NSTAGE - 2));
        __syncthreads();

        const int pf = kt + NSTAGE - 1;
        if (pf < ktiles) {
            int sp = sc + NSTAGE - 1; if (sp >= NSTAGE) sp -= NSTAGE;
            const __half* Ab = A + (pf << 6) + (pc << 3);
            const __half* Bb = B + (pf << 6) + (pc << 3);
            uint32_t Sa = smem_b + sp * STG_B + pc * 16;
            uint32_t Sb = Sa + TILE_A_B;
            #pragma unroll
            for (int l = 0; l < 4; l++) {
                const int r = pr + (l << 6);
                asm volatile("cp.async.cg.shared.global [%0], [%1], 16;"
                             :: "r"(Sa + r * ROW_B), "l"(Ab + (size_t)r * lda));
            }
            #pragma unroll
            for (int l = 0; l < 2; l++) {
                const int r = pr + (l << 6);
                asm volatile("cp.async.cg.shared.global [%0], [%1], 16;"
                             :: "r"(Sb + r * ROW_B), "l"(Bb + (size_t)r * ldb));
            }
        }
        asm volatile("cp.async.commit_group;");

        const uint32_t sbase = smem_b + sc * STG_B;
        const uint32_t aB = sbase + aoff;
        const uint32_t bB = sbase + boff;

        #pragma unroll
        for (int ks = 0; ks < 4; ks++) {
            const uint32_t kb = ks * 32;
            uint32_t a[4][4], b[4][2];
            #pragma unroll
            for (int mt = 0; mt < 4; mt++)
                asm volatile("ldmatrix.sync.aligned.m8n8.x4.shared.b16 {%0,%1,%2,%3}, [%4];"
                             : "=r"(a[mt][0]), "=r"(a[mt][1]), "=r"(a[mt][2]), "=r"(a[mt][3])
                             : "r"(aB + mt * (16 * ROW_B) + kb));
            asm volatile("ldmatrix.sync.aligned.m8n8.x4.shared.b16 {%0,%1,%2,%3}, [%4];"
                         : "=r"(b[0][0]), "=r"(b[0][1]), "=r"(b[1][0]), "=r"(b[1][1])
                         : "r"(bB + kb));
            asm volatile("ldmatrix.sync.aligned.m8n8.x4.shared.b16 {%0,%1,%2,%3}, [%4];"
                         : "=r"(b[2][0]), "=r"(b[2][1]), "=r"(b[3][0]), "=r"(b[3][1])
                         : "r"(bB + 16 * ROW_B + kb));
            #pragma unroll
            for (int mt = 0; mt < 4; mt++)
                #pragma unroll
                for (int nt = 0; nt < 4; nt++)
                    asm("mma.sync.aligned.m16n8k16.row.col.f32.f16.f16.f32 "
                        "{%0,%1,%2,%3}, {%4,%5,%6,%7}, {%8,%9}, {%0,%1,%2,%3};"
                        : "+f"(acc[mt][nt][0]), "+f"(acc[mt][nt][1]),
                          "+f"(acc[mt][nt][2]), "+f"(acc[mt][nt][3])
                        : "r"(a[mt][0]), "r"(a[mt][1]), "r"(a[mt][2]), "r"(a[mt][3]),
                          "r"(b[nt][0]), "r"(b[nt][1]));
        }
        if (++sc == NSTAGE) sc = 0;
    }

    // ---------------- epilogue ----------------
    const bool doStats = (rowSum != nullptr) || (bnSum != nullptr);
    if (doStats) {
        __syncthreads();
        if (tid < 256) { sm_r1[tid] = 0.0f; sm_r2[tid] = 0.0f; }
        __syncthreads();
    }
    #pragma unroll
    for (int mt = 0; mt < 4; mt++) {
        const int r0 = m0 + wm * 64 + mt * 16 + g;
        const float bm0 = biasM ? biasM[r0] : 0.0f;
        const float bm1 = biasM ? biasM[r0 + 8] : 0.0f;
        const float rs0 = rowScale ? rowScale[r0] : 1.0f;
        const float rs1 = rowScale ? rowScale[r0 + 8] : 1.0f;
        float s0 = 0.0f, s1 = 0.0f, q0 = 0.0f, q1 = 0.0f;
        #pragma unroll
        for (int nt = 0; nt < 4; nt++) {
            const int col = n0 + wn * 32 + nt * 8 + tg * 2;
            const float bn0 = biasN ? biasN[col] : 0.0f;
            const float bn1 = biasN ? biasN[col + 1] : 0.0f;
            float v0 = acc[mt][nt][0] * scale + bm0 + bn0;
            float v1 = acc[mt][nt][1] * scale + bm0 + bn1;
            float v2 = acc[mt][nt][2] * scale + bm1 + bn0;
            float v3 = acc[mt][nt][3] * scale + bm1 + bn1;
            if (rowSum) {
                v0 = (col     < nValid) ? __expf(v0) : 0.0f;
                v1 = (col + 1 < nValid) ? __expf(v1) : 0.0f;
                v2 = (col     < nValid) ? __expf(v2) : 0.0f;
                v3 = (col + 1 < nValid) ? __expf(v3) : 0.0f;
                s0 += v0 + v1; s1 += v2 + v3;
            }
            if (bnSum) {
                s0 += v0 + v1; s1 += v2 + v3;
                q0 += v0 * v0 + v1 * v1; q1 += v2 * v2 + v3 * v3;
            }
            v0 *= rs0; v1 *= rs0; v2 *= rs1; v3 *= rs1;
            st2(D + (size_t)r0 * ldd + col, v0, v1);
            st2(D + (size_t)(r0 + 8) * ldd + col, v2, v3);
        }
        if (doStats) {
            s0 += __shfl_xor_sync(0xffffffffu, s0, 1);
            s0 += __shfl_xor_sync(0xffffffffu, s0, 2);
            s1 += __shfl_xor_sync(0xffffffffu, s1, 1);
            s1 += __shfl_xor_sync(0xffffffffu, s1, 2);
            if (bnSum) {
                q0 += __shfl_xor_sync(0xffffffffu, q0, 1);
                q0 += __shfl_xor_sync(0xffffffffu, q0, 2);
                q1 += __shfl_xor_sync(0xffffffffu, q1, 1);
                q1 += __shfl_xor_sync(0xffffffffu, q1, 2);
            }
            if (tg == 0) {
                atomicAdd(&sm_r1[r0 - m0], s0);
                atomicAdd(&sm_r1[r0 + 8 - m0], s1);
                if (bnSum) {
                    atomicAdd(&sm_r2[r0 - m0], q0);
                    atomicAdd(&sm_r2[r0 + 8 - m0], q1);
                }
            }
        }
    }
    if (doStats) {
        __syncthreads();
        if (tid < 256) {
            if (rowSum) atomicAdd(&rowSum[m0 + tid], sm_r1[tid]);
            if (bnSum) {
                atomicAdd(&bnSum[m0 + tid], sm_r1[tid]);
                atomicAdd(&bnSq[m0 + tid],  sm_r2[tid]);
            }
        }
    }
}

// ---------------- fp32 -> fp16 weights + zero accumulators ----------------
__global__ void f2h4_kernel(const float* __restrict__ w0, const float* __restrict__ w1,
                            const float* __restrict__ w2, const float* __restrict__ w3)
{
    const int WSZ2 = CI * CC / 2;
    int i = blockIdx.x * 256 + threadIdx.x;
    int seg = i / WSZ2, off = i - seg * WSZ2;
    const float* s = (seg == 0) ? w0 : (seg == 1) ? w1 : (seg == 2) ? w2 : w3;
    __half* d = (seg == 0) ? d_thw : (seg == 1) ? d_phw : (seg == 2) ? d_gw : d_ww;
    float2 v = *(const float2*)(s + 2 * off);
    *(__half2*)(d + 2 * off) = __floats2half2_rn(v.x, v.y);
    if (i < BB * NQ) d_rowsum[i] = 0.0f;
    if (i < CC) { d_bnsum[i] = 0.0f; d_bnsq[i] = 0.0f; }
}

// ---------------- invert rowsum ----------------
__global__ void inv_rowsum_kernel()
{
    int i = blockIdx.x * 256 + threadIdx.x;
    if (i < BB * NQ) d_rowinv[i] = 1.0f / d_rowsum[i];
}

// ---------------- BN finalize ----------------
__global__ void bn_finalize_kernel()
{
    int c = blockIdx.x * 256 + threadIdx.x;
    if (c >= CC) return;
    const float cnt = (float)((long long)BB * NQ);
    float mean = d_bnsum[c] / cnt;
    float var = d_bnsq[c] / cnt - mean * mean;
    d_mean[c] = mean;
    d_istd[c] = rsqrtf(var + BN_EPS);
}

// ---------------- transpose x (B,C,NQ) -> xt fp16 (B,NQ,C) ----------------
__global__ void transpose_x(const float* __restrict__ x)
{
    __shared__ float t[32][33];
    const int b = blockIdx.z;
    const int n0 = blockIdx.x << 5, c0 = blockIdx.y << 5;
    const int tx = threadIdx.x, ty = threadIdx.y;
    const float* xp = x + (size_t)b * CC * NQ;
    __half* xo = d_xt + (size_t)b * NQ * CC;
    #pragma unroll
    for (int i = 0; i < 4; i++)
        t[ty + i*8][tx] = xp[(size_t)(c0 + ty + i*8) * NQ + n0 + tx];
    __syncthreads();
    #pragma unroll
    for (int i = 0; i < 4; i++)
        xo[(size_t)(n0 + ty + i*8) * CC + c0 + tx] = __float2half(t[tx][ty + i*8]);
}

// ---------------- pool xt -> xpt fp16 (B,NKp,C), pad rows zero -------------
__global__ void pool_kernel()
{
    const int b = blockIdx.y, nk = blockIdx.x;
    __half2* o = (__half2*)(d_xpt + ((size_t)b * NKp + nk) * CC);
    if (nk >= NKr) {
        for (int c = threadIdx.x; c < CC/2; c += 256) o[c] = __half2half2(__float2half(0.0f));
        return;
    }
    const int wi = nk % 14, hi = (nk / 14) % 14, t = nk / 196;
    const __half2* r0 = (const __half2*)(d_xt + ((size_t)b * NQ + (size_t)(t * HH + 2 * hi) * WW + 2 * wi) * CC);
    const int s1 = CC/2, s2 = WW*CC/2, s3 = (WW+1)*CC/2;
    for (int c = threadIdx.x; c < CC/2; c += 256)
        o[c] = __hmax2(__hmax2(r0[c], r0[s1 + c]), __hmax2(r0[s2 + c], r0[s3 + c]));
}

// ---------------- BN apply + residual (4 elems/thread) ----------------
__global__ void bn_apply_kernel(const float* __restrict__ x,
                                const float* __restrict__ gamma,
                                const float* __restrict__ beta,
                                float* __restrict__ out)
{
    size_t i = (size_t)blockIdx.x * 256 + threadIdx.x;   // quad index
    if (i >= (size_t)BB * CC * NQ / 4) return;
    int c = (int)((i / (NQ/4)) % CC);
    uint2 wraw = *(const uint2*)(d_wy + 4 * i);
    float2 wa = __half22float2(*(__half2*)&wraw.x);
    float2 wb = __half22float2(*(__half2*)&wraw.y);
    float4 xv = *(const float4*)(x + 4 * i);
    const float a = d_istd[c] * gamma[c];
    const float m = d_mean[c], bt = beta[c];
    float4 r;
    r.x = (wa.x - m) * a + bt + xv.x;
    r.y = (wa.y - m) * a + bt + xv.y;
    r.z = (wb.x - m) * a + bt + xv.z;
    r.w = (wb.y - m) * a + bt + xv.w;
    *(float4*)(out + 4 * i) = r;
}

// ---------------- host ----------------
extern "C" void kernel_launch(void* const* d_in, const int* in_sizes, int n_in,
                              void* d_out, int out_size)
{
    (void)in_sizes; (void)n_in; (void)out_size;
    const float* x       = (const float*)d_in[0];
    const float* theta_w = (const float*)d_in[1];
    const float* theta_b = (const float*)d_in[2];
    const float* phi_w   = (const float*)d_in[3];
    const float* phi_b   = (const float*)d_in[4];
    const float* g_w     = (const float*)d_in[5];
    const float* g_b     = (const float*)d_in[6];
    const float* w_w     = (const float*)d_in[7];
    const float* w_b     = (const float*)d_in[8];
    const float* bn_g    = (const float*)d_in[9];
    const float* bn_b    = (const float*)d_in[10];
    float* out = (float*)d_out;

    cudaFuncSetAttribute(gemm_tn<__half>, cudaFuncAttributeMaxDynamicSharedMemorySize, GEMM_SMEM);

    void *p_xt, *p_xpt, *p_th, *p_ph, *p_g2, *p_f, *p_y, *p_wy;
    void *p_thw, *p_phw, *p_gw, *p_ww, *p_rs, *p_ri, *p_bs, *p_bq;
    cudaGetSymbolAddress(&p_xt, d_xt);
    cudaGetSymbolAddress(&p_xpt, d_xpt);
    cudaGetSymbolAddress(&p_th, d_th);
    cudaGetSymbolAddress(&p_ph, d_ph);
    cudaGetSymbolAddress(&p_g2, d_g2);
    cudaGetSymbolAddress(&p_f, d_f);
    cudaGetSymbolAddress(&p_y, d_y);
    cudaGetSymbolAddress(&p_wy, d_wy);
    cudaGetSymbolAddress(&p_thw, d_thw);
    cudaGetSymbolAddress(&p_phw, d_phw);
    cudaGetSymbolAddress(&p_gw, d_gw);
    cudaGetSymbolAddress(&p_ww, d_ww);
    cudaGetSymbolAddress(&p_rs, d_rowsum);
    cudaGetSymbolAddress(&p_ri, d_rowinv);
    cudaGetSymbolAddress(&p_bs, d_bnsum);
    cudaGetSymbolAddress(&p_bq, d_bnsq);

    const float fscale = 1.0f / sqrtf((float)CI);

    f2h4_kernel<<<4 * CI * CC / 512, 256>>>(theta_w, phi_w, g_w, w_w);
    transpose_x<<<dim3(NQ/32, CC/32, BB), dim3(32,8)>>>(x);
    pool_kernel<<<dim3(NKp, BB), 256>>>();

    // theta (B,NQ,CI) = xt @ theta_w^T + theta_b[n]
    gemm_tn<__half><<<dim3(CI/128, NQ/256, BB), 512, GEMM_SMEM>>>(
        (const __half*)p_xt, (const __half*)p_thw, (__half*)p_th,
        CC, CC, CC, CI, (long long)NQ*CC, 0LL, (long long)NQ*CI,
        nullptr, theta_b, 1.0f, nullptr, nullptr, 0, 0LL, nullptr, nullptr);
    // phi (B,NKp,CI) = xpt @ phi_w^T + phi_b[n]
    gemm_tn<__half><<<dim3(CI/128, NKp/256, BB), 512, GEMM_SMEM>>>(
        (const __half*)p_xpt, (const __half*)p_phw, (__half*)p_ph,
        CC, CC, CC, CI, (long long)NKp*CC, 0LL, (long long)NKp*CI,
        nullptr, phi_b, 1.0f, nullptr, nullptr, 0, 0LL, nullptr, nullptr);
    // g2 (B,CI,NKp) = g_w @ xpt^T + g_b[m]
    gemm_tn<__half><<<dim3(NKp/128, CI/256, BB), 512, GEMM_SMEM>>>(
        (const __half*)p_gw, (const __half*)p_xpt, (__half*)p_g2,
        CC, CC, CC, NKp, 0LL, (long long)NKp*CC, (long long)CI*NKp,
        g_b, nullptr, 1.0f, nullptr, nullptr, 0, 0LL, nullptr, nullptr);
    // f (B,NQ,NKp) = exp(theta @ phi^T * scale), pad cols zero, rowsums
    gemm_tn<__half><<<dim3(NKp/128, NQ/256, BB), 512, GEMM_SMEM>>>(
        (const __half*)p_th, (const __half*)p_ph, (__half*)p_f,
        CI, CI, CI, NKp, (long long)NQ*CI, (long long)NKp*CI, (long long)NQ*NKp,
        nullptr, nullptr, fscale, (float*)p_rs, nullptr, NKr, (long long)NQ,
        nullptr, nullptr);

    inv_rowsum_kernel<<<(BB*NQ + 255)/256, 256>>>();

    // y (B,NQ,CI) = (expf @ g2^T) * rowinv[m]
    gemm_tn<__half><<<dim3(CI/128, NQ/256, BB), 512, GEMM_SMEM>>>(
        (const __half*)p_f, (const __half*)p_g2, (__half*)p_y,
        NKp, NKp, NKp, CI, (long long)NQ*NKp, (long long)CI*NKp, (long long)NQ*CI,
        nullptr, nullptr, 1.0f, nullptr, (const float*)p_ri, 0, (long long)NQ,
        nullptr, nullptr);
    // wy (B,CC,NQ) = w_w @ y^T + w_b[m], fused BN sum/sumsq
    gemm_tn<__half><<<dim3(NQ/128, CC/256, BB), 512, GEMM_SMEM>>>(
        (const __half*)p_ww, (const __half*)p_y, (__half*)p_wy,
        CI, CI, CI, NQ, 0LL, (long long)NQ*CI, (long long)CC*NQ,
        w_b, nullptr, 1.0f, nullptr, nullptr, 0, 0LL,
        (float*)p_bs, (float*)p_bq);

    bn_finalize_kernel<<<(CC + 255)/256, 256>>>();
    {
        size_t tot = (size_t)BB * CC * NQ / 4;
        bn_apply_kernel<<<(unsigned)((tot + 255) / 256), 256>>>(x, bn_g, bn_b, out);
    }
}

// round 13
// speedup vs baseline: 1.1691x; 1.1691x over previous
#include <cuda_runtime.h>
#include <cuda_fp16.h>
#include <math.h>
#include <stdint.h>

#define BB 4
#define CC 1024
#define CI 512
#define TT 16
#define HH 28
#define WW 28
#define NQ 12544
#define NKr 3136
#define NKp 3200
#define BN_EPS 1e-5f

// ---------------- scratch ----------------
__device__ __align__(256) __half d_xt  [(size_t)BB*NQ*CC];
__device__ __align__(256) __half d_xpt [(size_t)BB*NKp*CC];
__device__ __align__(256) __half d_th  [(size_t)BB*NQ*CI];
__device__ __align__(256) __half d_ph  [(size_t)BB*NKp*CI];
__device__ __align__(256) __half d_g2  [(size_t)BB*CI*NKp];
__device__ __align__(256) __half d_f   [(size_t)BB*NQ*NKp];   // exp(logits)
__device__ __align__(256) __half d_y   [(size_t)BB*NQ*CI];
__device__ __align__(256) __half d_wy  [(size_t)BB*CC*NQ];
__device__ __align__(256) __half d_thw [CI*CC];
__device__ __align__(256) __half d_phw [CI*CC];
__device__ __align__(256) __half d_gw  [CI*CC];
__device__ __align__(256) __half d_ww  [CC*CI];
__device__ float d_rowsum[(size_t)BB*NQ];
__device__ float d_bnsum[CC];
__device__ float d_bnsq [CC];
__device__ float d_mean[CC];
__device__ float d_istd[CC];

// ---------------- helpers ----------------
__device__ __forceinline__ uint32_t s2u(const void* p) {
    uint32_t a;
    asm("{ .reg .u64 t; cvta.to.shared.u64 t, %1; cvt.u32.u64 %0, t; }" : "=r"(a) : "l"(p));
    return a;
}
__device__ __forceinline__ void st2(float* p, float a, float b) {
    *(float2*)p = make_float2(a, b);
}
__device__ __forceinline__ void st2(__half* p, float a, float b) {
    *(__half2*)p = __floats2half2_rn(a, b);
}

// ---------------- fp16 mma.sync TN GEMM, CTA 128x128, warp 64x32, BK=64 ----
// D[M,N] = scale * A[M,K] @ B[N,K]^T (+ biasM[m]) (+ biasN[n])
// Fused epilogues:
//   rowSum : D = exp(val) (cols<nValid else 0), row sums -> rowSum[m] (per-batch)
//   rowRcp : D = val / rowRcp[m] (per-batch, reciprocal computed inline)
//   bnSum/bnSq: accumulate per-row sum / sumsq
#define ROW_B  144
#define TILE_B (128*ROW_B)
#define STG_B  (2*TILE_B)
#define NSTAGE 3
#define GEMM_SMEM (NSTAGE*STG_B)       // 110592 -> 2 CTAs/SM

template<typename TO>
__global__ __launch_bounds__(256, 2)
void gemm_tn(const __half* __restrict__ A, const __half* __restrict__ B,
             TO* __restrict__ D, int K, int lda, int ldb, int ldd,
             long long sA, long long sB, long long sD,
             const float* __restrict__ biasM, const float* __restrict__ biasN,
             float scale,
             float* __restrict__ rowSum, const float* __restrict__ rowRcp,
             int nValid, long long sR,
             float* __restrict__ bnSum, float* __restrict__ bnSq)
{
    extern __shared__ char smem[];
    __shared__ float sm_r1[128];
    __shared__ float sm_r2[128];
    const uint32_t smem_b = s2u(smem);
    const int tid = threadIdx.x, wid = tid >> 5, lane = tid & 31;
    const int wm = wid >> 2, wn = wid & 3;
    const int g = lane >> 2, tg = lane & 3;
    const int m0 = blockIdx.y << 7, n0 = blockIdx.x << 7;
    A += (long long)blockIdx.z * sA + (size_t)m0 * lda;
    B += (long long)blockIdx.z * sB + (size_t)n0 * ldb;
    D += (long long)blockIdx.z * sD;
    if (rowSum) rowSum += (long long)blockIdx.z * sR;
    if (rowRcp) rowRcp += (long long)blockIdx.z * sR;
    const int ktiles = K >> 6;

    const int prow[4] = { (tid + 0) >> 3, (tid + 256) >> 3, (tid + 512) >> 3, (tid + 768) >> 3 };
    const int pc = tid & 7;

    const uint32_t aoff = (uint32_t)(wm * 64 + (lane & 15)) * ROW_B + ((lane >> 4) << 4);
    const uint32_t boff = (uint32_t)TILE_B
                        + (uint32_t)(wn * 32 + ((lane >> 4) << 3) + (lane & 7)) * ROW_B
                        + (((lane >> 3) & 1) << 4);

    float acc[4][4][4];
    #pragma unroll
    for (int i = 0; i < 4; i++)
        #pragma unroll
        for (int j = 0; j < 4; j++)
            #pragma unroll
            for (int q = 0; q < 4; q++) acc[i][j][q] = 0.0f;

    // prologue: stages 0..NSTAGE-2
    #pragma unroll
    for (int s = 0; s < NSTAGE - 1; s++) {
        const __half* Ab = A + (s << 6) + (pc << 3);
        const __half* Bb = B + (s << 6) + (pc << 3);
        uint32_t Sa = smem_b + s * STG_B + pc * 16;
        uint32_t Sb = Sa + TILE_B;
        #pragma unroll
        for (int l = 0; l < 4; l++) {
            asm volatile("cp.async.cg.shared.global [%0], [%1], 16;"
                         :: "r"(Sa + prow[l] * ROW_B), "l"(Ab + (size_t)prow[l] * lda));
            asm volatile("cp.async.cg.shared.global [%0], [%1], 16;"
                         :: "r"(Sb + prow[l] * ROW_B), "l"(Bb + (size_t)prow[l] * ldb));
        }
        asm volatile("cp.async.commit_group;");
    }

    int sc = 0;
    for (int kt = 0; kt < ktiles; kt++) {
        asm volatile("cp.async.wait_group %0;" :: "n"(NSTAGE - 2));
        __syncthreads();

        // prefetch AFTER the barrier (single-barrier-safe overwrite ordering)
        const int pf = kt + NSTAGE - 1;
        if (pf < ktiles) {
            int sp = sc + NSTAGE - 1; if (sp >= NSTAGE) sp -= NSTAGE;
            const __half* Ab = A + (pf << 6) + (pc << 3);
            const __half* Bb = B + (pf << 6) + (pc << 3);
            uint32_t Sa = smem_b + sp * STG_B + pc * 16;
            uint32_t Sb = Sa + TILE_B;
            #pragma unroll
            for (int l = 0; l < 4; l++) {
                asm volatile("cp.async.cg.shared.global [%0], [%1], 16;"
                             :: "r"(Sa + prow[l] * ROW_B), "l"(Ab + (size_t)prow[l] * lda));
                asm volatile("cp.async.cg.shared.global [%0], [%1], 16;"
                             :: "r"(Sb + prow[l] * ROW_B), "l"(Bb + (size_t)prow[l] * ldb));
            }
        }
        asm volatile("cp.async.commit_group;");

        const uint32_t sbase = smem_b + sc * STG_B;
        const uint32_t aB = sbase + aoff;
        const uint32_t bB = sbase + boff;

        #pragma unroll
        for (int ks = 0; ks < 4; ks++) {
            const uint32_t kb = ks * 32;
            uint32_t a[4][4], b[4][2];
            #pragma unroll
            for (int mt = 0; mt < 4; mt++)
                asm volatile("ldmatrix.sync.aligned.m8n8.x4.shared.b16 {%0,%1,%2,%3}, [%4];"
                             : "=r"(a[mt][0]), "=r"(a[mt][1]), "=r"(a[mt][2]), "=r"(a[mt][3])
                             : "r"(aB + mt * (16 * ROW_B) + kb));
            asm volatile("ldmatrix.sync.aligned.m8n8.x4.shared.b16 {%0,%1,%2,%3}, [%4];"
                         : "=r"(b[0][0]), "=r"(b[0][1]), "=r"(b[1][0]), "=r"(b[1][1])
                         : "r"(bB + kb));
            asm volatile("ldmatrix.sync.aligned.m8n8.x4.shared.b16 {%0,%1,%2,%3}, [%4];"
                         : "=r"(b[2][0]), "=r"(b[2][1]), "=r"(b[3][0]), "=r"(b[3][1])
                         : "r"(bB + 16 * ROW_B + kb));
            #pragma unroll
            for (int mt = 0; mt < 4; mt++)
                #pragma unroll
                for (int nt = 0; nt < 4; nt++)
                    asm("mma.sync.aligned.m16n8k16.row.col.f32.f16.f16.f32 "
                        "{%0,%1,%2,%3}, {%4,%5,%6,%7}, {%8,%9}, {%0,%1,%2,%3};"
                        : "+f"(acc[mt][nt][0]), "+f"(acc[mt][nt][1]),
                          "+f"(acc[mt][nt][2]), "+f"(acc[mt][nt][3])
                        : "r"(a[mt][0]), "r"(a[mt][1]), "r"(a[mt][2]), "r"(a[mt][3]),
                          "r"(b[nt][0]), "r"(b[nt][1]));
        }
        if (++sc == NSTAGE) sc = 0;
    }

    // ---------------- epilogue ----------------
    const bool doStats = (rowSum != nullptr) || (bnSum != nullptr);
    if (doStats) {
        __syncthreads();
        if (tid < 128) { sm_r1[tid] = 0.0f; sm_r2[tid] = 0.0f; }
        __syncthreads();
    }
    #pragma unroll
    for (int mt = 0; mt < 4; mt++) {
        const int r0 = m0 + wm * 64 + mt * 16 + g;
        const float bm0 = biasM ? biasM[r0] : 0.0f;
        const float bm1 = biasM ? biasM[r0 + 8] : 0.0f;
        const float rs0 = rowRcp ? __frcp_rn(rowRcp[r0]) : 1.0f;
        const float rs1 = rowRcp ? __frcp_rn(rowRcp[r0 + 8]) : 1.0f;
        float s0 = 0.0f, s1 = 0.0f, q0 = 0.0f, q1 = 0.0f;
        #pragma unroll
        for (int nt = 0; nt < 4; nt++) {
            const int col = n0 + wn * 32 + nt * 8 + tg * 2;
            const float bn0 = biasN ? biasN[col] : 0.0f;
            const float bn1 = biasN ? biasN[col + 1] : 0.0f;
            float v0 = acc[mt][nt][0] * scale + bm0 + bn0;
            float v1 = acc[mt][nt][1] * scale + bm0 + bn1;
            float v2 = acc[mt][nt][2] * scale + bm1 + bn0;
            float v3 = acc[mt][nt][3] * scale + bm1 + bn1;
            if (rowSum) {
                v0 = (col     < nValid) ? __expf(v0) : 0.0f;
                v1 = (col + 1 < nValid) ? __expf(v1) : 0.0f;
                v2 = (col     < nValid) ? __expf(v2) : 0.0f;
                v3 = (col + 1 < nValid) ? __expf(v3) : 0.0f;
                s0 += v0 + v1; s1 += v2 + v3;
            }
            if (bnSum) {
                s0 += v0 + v1; s1 += v2 + v3;
                q0 += v0 * v0 + v1 * v1; q1 += v2 * v2 + v3 * v3;
            }
            v0 *= rs0; v1 *= rs0; v2 *= rs1; v3 *= rs1;
            st2(D + (size_t)r0 * ldd + col, v0, v1);
            st2(D + (size_t)(r0 + 8) * ldd + col, v2, v3);
        }
        if (doStats) {
            s0 += __shfl_xor_sync(0xffffffffu, s0, 1);
            s0 += __shfl_xor_sync(0xffffffffu, s0, 2);
            s1 += __shfl_xor_sync(0xffffffffu, s1, 1);
            s1 += __shfl_xor_sync(0xffffffffu, s1, 2);
            if (bnSum) {
                q0 += __shfl_xor_sync(0xffffffffu, q0, 1);
                q0 += __shfl_xor_sync(0xffffffffu, q0, 2);
                q1 += __shfl_xor_sync(0xffffffffu, q1, 1);
                q1 += __shfl_xor_sync(0xffffffffu, q1, 2);
            }
            if (tg == 0) {
                atomicAdd(&sm_r1[r0 - m0], s0);
                atomicAdd(&sm_r1[r0 + 8 - m0], s1);
                if (bnSum) {
                    atomicAdd(&sm_r2[r0 - m0], q0);
                    atomicAdd(&sm_r2[r0 + 8 - m0], q1);
                }
            }
        }
    }
    if (doStats) {
        __syncthreads();
        if (tid < 128) {
            if (rowSum) atomicAdd(&rowSum[m0 + tid], sm_r1[tid]);
            if (bnSum) {
                atomicAdd(&bnSum[m0 + tid], sm_r1[tid]);
                atomicAdd(&bnSq[m0 + tid],  sm_r2[tid]);
            }
        }
    }
}

// ---------------- fp32 -> fp16 weights + zero accumulators ----------------
__global__ void f2h4_kernel(const float* __restrict__ w0, const float* __restrict__ w1,
                            const float* __restrict__ w2, const float* __restrict__ w3)
{
    const int WSZ2 = CI * CC / 2;
    int i = blockIdx.x * 256 + threadIdx.x;
    int seg = i / WSZ2, off = i - seg * WSZ2;
    const float* s = (seg == 0) ? w0 : (seg == 1) ? w1 : (seg == 2) ? w2 : w3;
    __half* d = (seg == 0) ? d_thw : (seg == 1) ? d_phw : (seg == 2) ? d_gw : d_ww;
    float2 v = *(const float2*)(s + 2 * off);
    *(__half2*)(d + 2 * off) = __floats2half2_rn(v.x, v.y);
    if (i < BB * NQ) d_rowsum[i] = 0.0f;
    if (i < CC) { d_bnsum[i] = 0.0f; d_bnsq[i] = 0.0f; }
}

// ---------------- BN finalize ----------------
__global__ void bn_finalize_kernel()
{
    int c = blockIdx.x * 256 + threadIdx.x;
    if (c >= CC) return;
    const float cnt = (float)((long long)BB * NQ);
    float mean = d_bnsum[c] / cnt;
    float var = d_bnsq[c] / cnt - mean * mean;
    d_mean[c] = mean;
    d_istd[c] = rsqrtf(var + BN_EPS);
}

// ---------------- transpose x (B,C,NQ) -> xt fp16 (B,NQ,C) ----------------
__global__ void transpose_x(const float* __restrict__ x)
{
    __shared__ float t[32][33];
    const int b = blockIdx.z;
    const int n0 = blockIdx.x << 5, c0 = blockIdx.y << 5;
    const int tx = threadIdx.x, ty = threadIdx.y;
    const float* xp = x + (size_t)b * CC * NQ;
    __half* xo = d_xt + (size_t)b * NQ * CC;
    #pragma unroll
    for (int i = 0; i < 4; i++)
        t[ty + i*8][tx] = xp[(size_t)(c0 + ty + i*8) * NQ + n0 + tx];
    __syncthreads();
    #pragma unroll
    for (int i = 0; i < 4; i++)
        xo[(size_t)(n0 + ty + i*8) * CC + c0 + tx] = __float2half(t[tx][ty + i*8]);
}

// ---------------- pool xt -> xpt fp16 (B,NKp,C), pad rows zero -------------
__global__ void pool_kernel()
{
    const int b = blockIdx.y, nk = blockIdx.x;
    __half2* o = (__half2*)(d_xpt + ((size_t)b * NKp + nk) * CC);
    if (nk >= NKr) {
        for (int c = threadIdx.x; c < CC/2; c += 256) o[c] = __half2half2(__float2half(0.0f));
        return;
    }
    const int wi = nk % 14, hi = (nk / 14) % 14, t = nk / 196;
    const __half2* r0 = (const __half2*)(d_xt + ((size_t)b * NQ + (size_t)(t * HH + 2 * hi) * WW + 2 * wi) * CC);
    const int s1 = CC/2, s2 = WW*CC/2, s3 = (WW+1)*CC/2;
    for (int c = threadIdx.x; c < CC/2; c += 256)
        o[c] = __hmax2(__hmax2(r0[c], r0[s1 + c]), __hmax2(r0[s2 + c], r0[s3 + c]));
}

// ---------------- BN apply + residual (4 elems/thread) ----------------
__global__ void bn_apply_kernel(const float* __restrict__ x,
                                const float* __restrict__ gamma,
                                const float* __restrict__ beta,
                                float* __restrict__ out)
{
    size_t i = (size_t)blockIdx.x * 256 + threadIdx.x;   // quad index
    if (i >= (size_t)BB * CC * NQ / 4) return;
    int c = (int)((i / (NQ/4)) % CC);
    uint2 wraw = *(const uint2*)(d_wy + 4 * i);
    float2 wa = __half22float2(*(__half2*)&wraw.x);
    float2 wb = __half22float2(*(__half2*)&wraw.y);
    float4 xv = *(const float4*)(x + 4 * i);
    const float a = d_istd[c] * gamma[c];
    const float m = d_mean[c], bt = beta[c];
    float4 r;
    r.x = (wa.x - m) * a + bt + xv.x;
    r.y = (wa.y - m) * a + bt + xv.y;
    r.z = (wb.x - m) * a + bt + xv.z;
    r.w = (wb.y - m) * a + bt + xv.w;
    *(float4*)(out + 4 * i) = r;
}

// ---------------- host ----------------
extern "C" void kernel_launch(void* const* d_in, const int* in_sizes, int n_in,
                              void* d_out, int out_size)
{
    (void)in_sizes; (void)n_in; (void)out_size;
    const float* x       = (const float*)d_in[0];
    const float* theta_w = (const float*)d_in[1];
    const float* theta_b = (const float*)d_in[2];
    const float* phi_w   = (const float*)d_in[3];
    const float* phi_b   = (const float*)d_in[4];
    const float* g_w     = (const float*)d_in[5];
    const float* g_b     = (const float*)d_in[6];
    const float* w_w     = (const float*)d_in[7];
    const float* w_b     = (const float*)d_in[8];
    const float* bn_g    = (const float*)d_in[9];
    const float* bn_b    = (const float*)d_in[10];
    float* out = (float*)d_out;

    cudaFuncSetAttribute(gemm_tn<__half>, cudaFuncAttributeMaxDynamicSharedMemorySize, GEMM_SMEM);

    void *p_xt, *p_xpt, *p_th, *p_ph, *p_g2, *p_f, *p_y, *p_wy;
    void *p_thw, *p_phw, *p_gw, *p_ww, *p_rs, *p_bs, *p_bq;
    cudaGetSymbolAddress(&p_xt, d_xt);
    cudaGetSymbolAddress(&p_xpt, d_xpt);
    cudaGetSymbolAddress(&p_th, d_th);
    cudaGetSymbolAddress(&p_ph, d_ph);
    cudaGetSymbolAddress(&p_g2, d_g2);
    cudaGetSymbolAddress(&p_f, d_f);
    cudaGetSymbolAddress(&p_y, d_y);
    cudaGetSymbolAddress(&p_wy, d_wy);
    cudaGetSymbolAddress(&p_thw, d_thw);
    cudaGetSymbolAddress(&p_phw, d_phw);
    cudaGetSymbolAddress(&p_gw, d_gw);
    cudaGetSymbolAddress(&p_ww, d_ww);
    cudaGetSymbolAddress(&p_rs, d_rowsum);
    cudaGetSymbolAddress(&p_bs, d_bnsum);
    cudaGetSymbolAddress(&p_bq, d_bnsq);

    const float fscale = 1.0f / sqrtf((float)CI);

    f2h4_kernel<<<4 * CI * CC / 512, 256>>>(theta_w, phi_w, g_w, w_w);
    transpose_x<<<dim3(NQ/32, CC/32, BB), dim3(32,8)>>>(x);
    pool_kernel<<<dim3(NKp, BB), 256>>>();

    // theta (B,NQ,CI) = xt @ theta_w^T + theta_b[n]
    gemm_tn<__half><<<dim3(CI/128, NQ/128, BB), 256, GEMM_SMEM>>>(
        (const __half*)p_xt, (const __half*)p_thw, (__half*)p_th,
        CC, CC, CC, CI, (long long)NQ*CC, 0LL, (long long)NQ*CI,
        nullptr, theta_b, 1.0f, nullptr, nullptr, 0, 0LL, nullptr, nullptr);
    // phi (B,NKp,CI) = xpt @ phi_w^T + phi_b[n]
    gemm_tn<__half><<<dim3(CI/128, NKp/128, BB), 256, GEMM_SMEM>>>(
        (const __half*)p_xpt, (const __half*)p_phw, (__half*)p_ph,
        CC, CC, CC, CI, (long long)NKp*CC, 0LL, (long long)NKp*CI,
        nullptr, phi_b, 1.0f, nullptr, nullptr, 0, 0LL, nullptr, nullptr);
    // g2 (B,CI,NKp) = g_w @ xpt^T + g_b[m]
    gemm_tn<__half><<<dim3(NKp/128, CI/128, BB), 256, GEMM_SMEM>>>(
        (const __half*)p_gw, (const __half*)p_xpt, (__half*)p_g2,
        CC, CC, CC, NKp, 0LL, (long long)NKp*CC, (long long)CI*NKp,
        g_b, nullptr, 1.0f, nullptr, nullptr, 0, 0LL, nullptr, nullptr);
    // f (B,NQ,NKp) = exp(theta @ phi^T * scale), pad cols zero, rowsums
    gemm_tn<__half><<<dim3(NKp/128, NQ/128, BB), 256, GEMM_SMEM>>>(
        (const __half*)p_th, (const __half*)p_ph, (__half*)p_f,
        CI, CI, CI, NKp, (long long)NQ*CI, (long long)NKp*CI, (long long)NQ*NKp,
        nullptr, nullptr, fscale, (float*)p_rs, nullptr, NKr, (long long)NQ,
        nullptr, nullptr);

    // y (B,NQ,CI) = (expf @ g2^T) / rowsum[m]   (rcp computed in epilogue)
    gemm_tn<__half><<<dim3(CI/128, NQ/128, BB), 256, GEMM_SMEM>>>(
        (const __half*)p_f, (const __half*)p_g2, (__half*)p_y,
        NKp, NKp, NKp, CI, (long long)NQ*NKp, (long long)CI*NKp, (long long)NQ*CI,
        nullptr, nullptr, 1.0f, nullptr, (const float*)p_rs, 0, (long long)NQ,
        nullptr, nullptr);
    // wy (B,CC,NQ) = w_w @ y^T + w_b[m], fused BN sum/sumsq
    gemm_tn<__half><<<dim3(NQ/128, CC/128, BB), 256, GEMM_SMEM>>>(
        (const __half*)p_ww, (const __half*)p_y, (__half*)p_wy,
        CI, CI, CI, NQ, 0LL, (long long)NQ*CI, (long long)CC*NQ,
        w_b, nullptr, 1.0f, nullptr, nullptr, 0, 0LL,
        (float*)p_bs, (float*)p_bq);

    bn_finalize_kernel<<<(CC + 255)/256, 256>>>();
    {
        size_t tot = (size_t)BB * CC * NQ / 4;
        bn_apply_kernel<<<(unsigned)((tot + 255) / 256), 256>>>(x, bn_g, bn_b, out);
    }
}

// round 14
// speedup vs baseline: 1.1874x; 1.0157x over previous
#include <cuda_runtime.h>
#include <cuda_fp16.h>
#include <math.h>
#include <stdint.h>

#define BB 4
#define CC 1024
#define CI 512
#define TT 16
#define HH 28
#define WW 28
#define NQ 12544
#define NKr 3136
#define NKp 3200
#define BN_EPS 1e-5f

// ---------------- scratch ----------------
__device__ __align__(256) __half d_xt  [(size_t)BB*NQ*CC];
__device__ __align__(256) __half d_xpt [(size_t)BB*NKp*CC];
__device__ __align__(256) __half d_th  [(size_t)BB*NQ*CI];
__device__ __align__(256) __half d_ph  [(size_t)BB*NKp*CI];
__device__ __align__(256) __half d_g2  [(size_t)BB*CI*NKp];
__device__ __align__(256) __half d_f   [(size_t)BB*NQ*NKp];   // exp(logits)
__device__ __align__(256) __half d_y   [(size_t)BB*NQ*CI];
__device__ __align__(256) __half d_wy  [(size_t)BB*CC*NQ];
__device__ __align__(256) __half d_thw [CI*CC];
__device__ __align__(256) __half d_phw [CI*CC];
__device__ __align__(256) __half d_gw  [CI*CC];
__device__ __align__(256) __half d_ww  [CC*CI];
__device__ float d_rowsum[(size_t)BB*NQ];
__device__ float d_bnsum[CC];
__device__ float d_bnsq [CC];
__device__ float d_mean[CC];
__device__ float d_istd[CC];

// ---------------- helpers ----------------
__device__ __forceinline__ uint32_t s2u(const void* p) {
    uint32_t a;
    asm("{ .reg .u64 t; cvta.to.shared.u64 t, %1; cvt.u32.u64 %0, t; }" : "=r"(a) : "l"(p));
    return a;
}
__device__ __forceinline__ void st2(float* p, float a, float b) {
    *(float2*)p = make_float2(a, b);
}
__device__ __forceinline__ void st2(__half* p, float a, float b) {
    *(__half2*)p = __floats2half2_rn(a, b);
}

// ---------------- fp16 mma.sync TN GEMM core ----------------
// CTA 128x128, warp 64x32, BK=64, NSTAGE=3, 2 CTAs/SM.
// D[M,N] = scale * A[M,K] @ B[N,K]^T (+ biasM[m]) (+ biasN[n])
// rowSum : D = exp2(val) (cols<nValid else 0), row sums -> rowSum[m]
// rowRcp : D = val / rowRcp[m] (rcp inline)
// bnSum/bnSq : per-row sum/sumsq accumulation
#define ROW_B  144
#define TILE_B (128*ROW_B)
#define STG_B  (2*TILE_B)
#define NSTAGE 3
#define GEMM_SMEM (NSTAGE*STG_B)       // 110592 -> 2 CTAs/SM

template<typename TO>
__device__ __forceinline__ void gemm_dev(
    const __half* __restrict__ A, const __half* __restrict__ B,
    TO* __restrict__ D, int K, int lda, int ldb, int ldd,
    long long sA, long long sB, long long sD,
    const float* __restrict__ biasM, const float* __restrict__ biasN,
    float scale,
    float* __restrict__ rowSum, const float* __restrict__ rowRcp,
    int nValid, long long sR,
    float* __restrict__ bnSum, float* __restrict__ bnSq,
    int bx, int by, int bz)
{
    extern __shared__ char smem[];
    __shared__ float sm_r1[128];
    __shared__ float sm_r2[128];
    const uint32_t smem_b = s2u(smem);
    const int tid = threadIdx.x, wid = tid >> 5, lane = tid & 31;
    const int wm = wid >> 2, wn = wid & 3;
    const int g = lane >> 2, tg = lane & 3;
    const int m0 = by << 7, n0 = bx << 7;
    A += (long long)bz * sA + (size_t)m0 * lda;
    B += (long long)bz * sB + (size_t)n0 * ldb;
    D += (long long)bz * sD;
    if (rowSum) rowSum += (long long)bz * sR;
    if (rowRcp) rowRcp += (long long)bz * sR;
    const int ktiles = K >> 6;

    const int prow[4] = { (tid + 0) >> 3, (tid + 256) >> 3, (tid + 512) >> 3, (tid + 768) >> 3 };
    const int pc = tid & 7;

    const uint32_t aoff = (uint32_t)(wm * 64 + (lane & 15)) * ROW_B + ((lane >> 4) << 4);
    const uint32_t boff = (uint32_t)TILE_B
                        + (uint32_t)(wn * 32 + ((lane >> 4) << 3) + (lane & 7)) * ROW_B
                        + (((lane >> 3) & 1) << 4);

    float acc[4][4][4];
    #pragma unroll
    for (int i = 0; i < 4; i++)
        #pragma unroll
        for (int j = 0; j < 4; j++)
            #pragma unroll
            for (int q = 0; q < 4; q++) acc[i][j][q] = 0.0f;

    #pragma unroll
    for (int s = 0; s < NSTAGE - 1; s++) {
        const __half* Ab = A + (s << 6) + (pc << 3);
        const __half* Bb = B + (s << 6) + (pc << 3);
        uint32_t Sa = smem_b + s * STG_B + pc * 16;
        uint32_t Sb = Sa + TILE_B;
        #pragma unroll
        for (int l = 0; l < 4; l++) {
            asm volatile("cp.async.cg.shared.global [%0], [%1], 16;"
                         :: "r"(Sa + prow[l] * ROW_B), "l"(Ab + (size_t)prow[l] * lda));
            asm volatile("cp.async.cg.shared.global [%0], [%1], 16;"
                         :: "r"(Sb + prow[l] * ROW_B), "l"(Bb + (size_t)prow[l] * ldb));
        }
        asm volatile("cp.async.commit_group;");
    }

    int sc = 0;
    for (int kt = 0; kt < ktiles; kt++) {
        asm volatile("cp.async.wait_group %0;" :: "n"(NSTAGE - 2));
        __syncthreads();

        const int pf = kt + NSTAGE - 1;
        if (pf < ktiles) {
            int sp = sc + NSTAGE - 1; if (sp >= NSTAGE) sp -= NSTAGE;
            const __half* Ab = A + (pf << 6) + (pc << 3);
            const __half* Bb = B + (pf << 6) + (pc << 3);
            uint32_t Sa = smem_b + sp * STG_B + pc * 16;
            uint32_t Sb = Sa + TILE_B;
            #pragma unroll
            for (int l = 0; l < 4; l++) {
                asm volatile("cp.async.cg.shared.global [%0], [%1], 16;"
                             :: "r"(Sa + prow[l] * ROW_B), "l"(Ab + (size_t)prow[l] * lda));
                asm volatile("cp.async.cg.shared.global [%0], [%1], 16;"
                             :: "r"(Sb + prow[l] * ROW_B), "l"(Bb + (size_t)prow[l] * ldb));
            }
        }
        asm volatile("cp.async.commit_group;");

        const uint32_t sbase = smem_b + sc * STG_B;
        const uint32_t aB = sbase + aoff;
        const uint32_t bB = sbase + boff;

        #pragma unroll
        for (int ks = 0; ks < 4; ks++) {
            const uint32_t kb = ks * 32;
            uint32_t a[4][4], b[4][2];
            #pragma unroll
            for (int mt = 0; mt < 4; mt++)
                asm volatile("ldmatrix.sync.aligned.m8n8.x4.shared.b16 {%0,%1,%2,%3}, [%4];"
                             : "=r"(a[mt][0]), "=r"(a[mt][1]), "=r"(a[mt][2]), "=r"(a[mt][3])
                             : "r"(aB + mt * (16 * ROW_B) + kb));
            asm volatile("ldmatrix.sync.aligned.m8n8.x4.shared.b16 {%0,%1,%2,%3}, [%4];"
                         : "=r"(b[0][0]), "=r"(b[0][1]), "=r"(b[1][0]), "=r"(b[1][1])
                         : "r"(bB + kb));
            asm volatile("ldmatrix.sync.aligned.m8n8.x4.shared.b16 {%0,%1,%2,%3}, [%4];"
                         : "=r"(b[2][0]), "=r"(b[2][1]), "=r"(b[3][0]), "=r"(b[3][1])
                         : "r"(bB + 16 * ROW_B + kb));
            #pragma unroll
            for (int mt = 0; mt < 4; mt++)
                #pragma unroll
                for (int nt = 0; nt < 4; nt++)
                    asm("mma.sync.aligned.m16n8k16.row.col.f32.f16.f16.f32 "
                        "{%0,%1,%2,%3}, {%4,%5,%6,%7}, {%8,%9}, {%0,%1,%2,%3};"
                        : "+f"(acc[mt][nt][0]), "+f"(acc[mt][nt][1]),
                          "+f"(acc[mt][nt][2]), "+f"(acc[mt][nt][3])
                        : "r"(a[mt][0]), "r"(a[mt][1]), "r"(a[mt][2]), "r"(a[mt][3]),
                          "r"(b[nt][0]), "r"(b[nt][1]));
        }
        if (++sc == NSTAGE) sc = 0;
    }

    // ---------------- epilogue ----------------
    const bool doStats = (rowSum != nullptr) || (bnSum != nullptr);
    if (doStats) {
        __syncthreads();
        if (tid < 128) { sm_r1[tid] = 0.0f; sm_r2[tid] = 0.0f; }
        __syncthreads();
    }
    #pragma unroll
    for (int mt = 0; mt < 4; mt++) {
        const int r0 = m0 + wm * 64 + mt * 16 + g;
        const float bm0 = biasM ? biasM[r0] : 0.0f;
        const float bm1 = biasM ? biasM[r0 + 8] : 0.0f;
        const float rs0 = rowRcp ? __frcp_rn(rowRcp[r0]) : 1.0f;
        const float rs1 = rowRcp ? __frcp_rn(rowRcp[r0 + 8]) : 1.0f;
        float s0 = 0.0f, s1 = 0.0f, q0 = 0.0f, q1 = 0.0f;
        #pragma unroll
        for (int nt = 0; nt < 4; nt++) {
            const int col = n0 + wn * 32 + nt * 8 + tg * 2;
            const float bn0 = biasN ? biasN[col] : 0.0f;
            const float bn1 = biasN ? biasN[col + 1] : 0.0f;
            float v0 = acc[mt][nt][0] * scale + bm0 + bn0;
            float v1 = acc[mt][nt][1] * scale + bm0 + bn1;
            float v2 = acc[mt][nt][2] * scale + bm1 + bn0;
            float v3 = acc[mt][nt][3] * scale + bm1 + bn1;
            if (rowSum) {
                // scale already includes log2(e): exp(x) == exp2(x*log2e)
                v0 = (col     < nValid) ? exp2f(v0) : 0.0f;
                v1 = (col + 1 < nValid) ? exp2f(v1) : 0.0f;
                v2 = (col     < nValid) ? exp2f(v2) : 0.0f;
                v3 = (col + 1 < nValid) ? exp2f(v3) : 0.0f;
                s0 += v0 + v1; s1 += v2 + v3;
            }
            if (bnSum) {
                s0 += v0 + v1; s1 += v2 + v3;
                q0 += v0 * v0 + v1 * v1; q1 += v2 * v2 + v3 * v3;
            }
            v0 *= rs0; v1 *= rs0; v2 *= rs1; v3 *= rs1;
            st2(D + (size_t)r0 * ldd + col, v0, v1);
            st2(D + (size_t)(r0 + 8) * ldd + col, v2, v3);
        }
        if (doStats) {
            s0 += __shfl_xor_sync(0xffffffffu, s0, 1);
            s0 += __shfl_xor_sync(0xffffffffu, s0, 2);
            s1 += __shfl_xor_sync(0xffffffffu, s1, 1);
            s1 += __shfl_xor_sync(0xffffffffu, s1, 2);
            if (bnSum) {
                q0 += __shfl_xor_sync(0xffffffffu, q0, 1);
                q0 += __shfl_xor_sync(0xffffffffu, q0, 2);
                q1 += __shfl_xor_sync(0xffffffffu, q1, 1);
                q1 += __shfl_xor_sync(0xffffffffu, q1, 2);
            }
            if (tg == 0) {
                atomicAdd(&sm_r1[r0 - m0], s0);
                atomicAdd(&sm_r1[r0 + 8 - m0], s1);
                if (bnSum) {
                    atomicAdd(&sm_r2[r0 - m0], q0);
                    atomicAdd(&sm_r2[r0 + 8 - m0], q1);
                }
            }
        }
    }
    if (doStats) {
        __syncthreads();
        if (tid < 128) {
            if (rowSum) atomicAdd(&rowSum[m0 + tid], sm_r1[tid]);
            if (bnSum) {
                atomicAdd(&bnSum[m0 + tid], sm_r1[tid]);
                atomicAdd(&bnSq[m0 + tid],  sm_r2[tid]);
            }
        }
    }
}

// Standard single-GEMM launcher
template<typename TO>
__global__ __launch_bounds__(256, 2)
void gemm_tn(const __half* __restrict__ A, const __half* __restrict__ B,
             TO* __restrict__ D, int K, int lda, int ldb, int ldd,
             long long sA, long long sB, long long sD,
             const float* __restrict__ biasM, const float* __restrict__ biasN,
             float scale,
             float* __restrict__ rowSum, const float* __restrict__ rowRcp,
             int nValid, long long sR,
             float* __restrict__ bnSum, float* __restrict__ bnSq)
{
    gemm_dev<TO>(A, B, D, K, lda, ldb, ldd, sA, sB, sD, biasM, biasN, scale,
                 rowSum, rowRcp, nValid, sR, bnSum, bnSq,
                 blockIdx.x, blockIdx.y, blockIdx.z);
}

// Merged theta+phi+g2 projections: one flat grid, tails pack.
// theta: 1568 CTAs (4x98x4), phi: 400 (4x25x4), g2: 400 (25x4x4)
#define PROJ3_GRID 2368
__global__ __launch_bounds__(256, 2)
void proj3_kernel(const float* __restrict__ theta_b,
                  const float* __restrict__ phi_b,
                  const float* __restrict__ g_b)
{
    const int t = blockIdx.x;
    const __half *A, *B;
    __half* D;
    int ldd, bx, by, bz;
    long long sA, sB, sD;
    const float *bM, *bN;
    if (t < 1568) {
        int r = t; bz = r / 392; r -= bz * 392; by = r >> 2; bx = r & 3;
        A = d_xt; B = d_thw; D = d_th; ldd = CI;
        sA = (long long)NQ * CC; sB = 0; sD = (long long)NQ * CI;
        bM = nullptr; bN = theta_b;
    } else if (t < 1968) {
        int r = t - 1568; bz = r / 100; r -= bz * 100; by = r >> 2; bx = r & 3;
        A = d_xpt; B = d_phw; D = d_ph; ldd = CI;
        sA = (long long)NKp * CC; sB = 0; sD = (long long)NKp * CI;
        bM = nullptr; bN = phi_b;
    } else {
        int r = t - 1968; bz = r / 100; r -= bz * 100; by = r / 25; bx = r - by * 25;
        A = d_gw; B = d_xpt; D = d_g2; ldd = NKp;
        sA = 0; sB = (long long)NKp * CC; sD = (long long)CI * NKp;
        bM = g_b; bN = nullptr;
    }
    gemm_dev<__half>(A, B, D, CC, CC, CC, ldd, sA, sB, sD, bM, bN, 1.0f,
                     nullptr, nullptr, 0, 0LL, nullptr, nullptr, bx, by, bz);
}

// ---------------- fp32 -> fp16 weights + zero accumulators ----------------
__global__ void f2h4_kernel(const float* __restrict__ w0, const float* __restrict__ w1,
                            const float* __restrict__ w2, const float* __restrict__ w3)
{
    const int WSZ2 = CI * CC / 2;
    int i = blockIdx.x * 256 + threadIdx.x;
    int seg = i / WSZ2, off = i - seg * WSZ2;
    const float* s = (seg == 0) ? w0 : (seg == 1) ? w1 : (seg == 2) ? w2 : w3;
    __half* d = (seg == 0) ? d_thw : (seg == 1) ? d_phw : (seg == 2) ? d_gw : d_ww;
    float2 v = *(const float2*)(s + 2 * off);
    *(__half2*)(d + 2 * off) = __floats2half2_rn(v.x, v.y);
    if (i < BB * NQ) d_rowsum[i] = 0.0f;
    if (i < CC) { d_bnsum[i] = 0.0f; d_bnsq[i] = 0.0f; }
}

// ---------------- BN finalize ----------------
__global__ void bn_finalize_kernel()
{
    int c = blockIdx.x * 256 + threadIdx.x;
    if (c >= CC) return;
    const float cnt = (float)((long long)BB * NQ);
    float mean = d_bnsum[c] / cnt;
    float var = d_bnsq[c] / cnt - mean * mean;
    d_mean[c] = mean;
    d_istd[c] = rsqrtf(var + BN_EPS);
}

// ---------------- transpose x (B,C,NQ) -> xt fp16 (B,NQ,C) ----------------
__global__ void transpose_x(const float* __restrict__ x)
{
    __shared__ float t[32][33];
    const int b = blockIdx.z;
    const int n0 = blockIdx.x << 5, c0 = blockIdx.y << 5;
    const int tx = threadIdx.x, ty = threadIdx.y;
    const float* xp = x + (size_t)b * CC * NQ;
    __half* xo = d_xt + (size_t)b * NQ * CC;
    #pragma unroll
    for (int i = 0; i < 4; i++)
        t[ty + i*8][tx] = xp[(size_t)(c0 + ty + i*8) * NQ + n0 + tx];
    __syncthreads();
    #pragma unroll
    for (int i = 0; i < 4; i++)
        xo[(size_t)(n0 + ty + i*8) * CC + c0 + tx] = __float2half(t[tx][ty + i*8]);
}

// ---------------- pool xt -> xpt fp16 (B,NKp,C), pad rows zero -------------
__global__ void pool_kernel()
{
    const int b = blockIdx.y, nk = blockIdx.x;
    __half2* o = (__half2*)(d_xpt + ((size_t)b * NKp + nk) * CC);
    if (nk >= NKr) {
        for (int c = threadIdx.x; c < CC/2; c += 256) o[c] = __half2half2(__float2half(0.0f));
        return;
    }
    const int wi = nk % 14, hi = (nk / 14) % 14, t = nk / 196;
    const __half2* r0 = (const __half2*)(d_xt + ((size_t)b * NQ + (size_t)(t * HH + 2 * hi) * WW + 2 * wi) * CC);
    const int s1 = CC/2, s2 = WW*CC/2, s3 = (WW+1)*CC/2;
    for (int c = threadIdx.x; c < CC/2; c += 256)
        o[c] = __hmax2(__hmax2(r0[c], r0[s1 + c]), __hmax2(r0[s2 + c], r0[s3 + c]));
}

// ---------------- BN apply + residual (4 elems/thread) ----------------
__global__ void bn_apply_kernel(const float* __restrict__ x,
                                const float* __restrict__ gamma,
                                const float* __restrict__ beta,
                                float* __restrict__ out)
{
    size_t i = (size_t)blockIdx.x * 256 + threadIdx.x;   // quad index
    if (i >= (size_t)BB * CC * NQ / 4) return;
    int c = (int)((i / (NQ/4)) % CC);
    uint2 wraw = *(const uint2*)(d_wy + 4 * i);
    float2 wa = __half22float2(*(__half2*)&wraw.x);
    float2 wb = __half22float2(*(__half2*)&wraw.y);
    float4 xv = *(const float4*)(x + 4 * i);
    const float a = d_istd[c] * gamma[c];
    const float m = d_mean[c], bt = beta[c];
    float4 r;
    r.x = (wa.x - m) * a + bt + xv.x;
    r.y = (wa.y - m) * a + bt + xv.y;
    r.z = (wb.x - m) * a + bt + xv.z;
    r.w = (wb.y - m) * a + bt + xv.w;
    *(float4*)(out + 4 * i) = r;
}

// ---------------- host ----------------
extern "C" void kernel_launch(void* const* d_in, const int* in_sizes, int n_in,
                              void* d_out, int out_size)
{
    (void)in_sizes; (void)n_in; (void)out_size;
    const float* x       = (const float*)d_in[0];
    const float* theta_w = (const float*)d_in[1];
    const float* theta_b = (const float*)d_in[2];
    const float* phi_w   = (const float*)d_in[3];
    const float* phi_b   = (const float*)d_in[4];
    const float* g_w     = (const float*)d_in[5];
    const float* g_b     = (const float*)d_in[6];
    const float* w_w     = (const float*)d_in[7];
    const float* w_b     = (const float*)d_in[8];
    const float* bn_g    = (const float*)d_in[9];
    const float* bn_b    = (const float*)d_in[10];
    float* out = (float*)d_out;

    cudaFuncSetAttribute(gemm_tn<__half>, cudaFuncAttributeMaxDynamicSharedMemorySize, GEMM_SMEM);
    cudaFuncSetAttribute(proj3_kernel, cudaFuncAttributeMaxDynamicSharedMemorySize, GEMM_SMEM);

    void *p_th, *p_ph, *p_g2, *p_f, *p_y, *p_wy, *p_ww, *p_rs, *p_bs, *p_bq;
    cudaGetSymbolAddress(&p_th, d_th);
    cudaGetSymbolAddress(&p_ph, d_ph);
    cudaGetSymbolAddress(&p_g2, d_g2);
    cudaGetSymbolAddress(&p_f, d_f);
    cudaGetSymbolAddress(&p_y, d_y);
    cudaGetSymbolAddress(&p_wy, d_wy);
    cudaGetSymbolAddress(&p_ww, d_ww);
    cudaGetSymbolAddress(&p_rs, d_rowsum);
    cudaGetSymbolAddress(&p_bs, d_bnsum);
    cudaGetSymbolAddress(&p_bq, d_bnsq);

    const float fscale2 = 1.442695040888963f / sqrtf((float)CI);  // log2e folded

    f2h4_kernel<<<4 * CI * CC / 512, 256>>>(theta_w, phi_w, g_w, w_w);
    transpose_x<<<dim3(NQ/32, CC/32, BB), dim3(32,8)>>>(x);
    pool_kernel<<<dim3(NKp, BB), 256>>>();

    // theta + phi + g2 in one packed launch
    proj3_kernel<<<PROJ3_GRID, 256, GEMM_SMEM>>>(theta_b, phi_b, g_b);

    // f (B,NQ,NKp) = exp(theta @ phi^T * scale), pad cols zero, rowsums
    gemm_tn<__half><<<dim3(NKp/128, NQ/128, BB), 256, GEMM_SMEM>>>(
        (const __half*)p_th, (const __half*)p_ph, (__half*)p_f,
        CI, CI, CI, NKp, (long long)NQ*CI, (long long)NKp*CI, (long long)NQ*NKp,
        nullptr, nullptr, fscale2, (float*)p_rs, nullptr, NKr, (long long)NQ,
        nullptr, nullptr);

    // y (B,NQ,CI) = (expf @ g2^T) / rowsum[m]
    gemm_tn<__half><<<dim3(CI/128, NQ/128, BB), 256, GEMM_SMEM>>>(
        (const __half*)p_f, (const __half*)p_g2, (__half*)p_y,
        NKp, NKp, NKp, CI, (long long)NQ*NKp, (long long)CI*NKp, (long long)NQ*CI,
        nullptr, nullptr, 1.0f, nullptr, (const float*)p_rs, 0, (long long)NQ,
        nullptr, nullptr);
    // wy (B,CC,NQ) = w_w @ y^T + w_b[m], fused BN sum/sumsq
    gemm_tn<__half><<<dim3(NQ/128, CC/128, BB), 256, GEMM_SMEM>>>(
        (const __half*)p_ww, (const __half*)p_y, (__half*)p_wy,
        CI, CI, CI, NQ, 0LL, (long long)NQ*CI, (long long)CC*NQ,
        w_b, nullptr, 1.0f, nullptr, nullptr, 0, 0LL,
        (float*)p_bs, (float*)p_bq);

    bn_finalize_kernel<<<(CC + 255)/256, 256>>>();
    {
        size_t tot = (size_t)BB * CC * NQ / 4;
        bn_apply_kernel<<<(unsigned)((tot + 255) / 256), 256>>>(x, bn_g, bn_b, out);
    }
}

// round 15
// speedup vs baseline: 1.2279x; 1.0341x over previous
#include <cuda_runtime.h>
#include <cuda_fp16.h>
#include <math.h>
#include <stdint.h>

#define BB 4
#define CC 1024
#define CI 512
#define TT 16
#define HH 28
#define WW 28
#define NQ 12544
#define NKr 3136
#define NKp 3200
#define BN_EPS 1e-5f

// ---------------- scratch ----------------
__device__ __align__(256) __half d_xt  [(size_t)BB*NQ*CC];
__device__ __align__(256) __half d_xpt [(size_t)BB*NKp*CC];
__device__ __align__(256) __half d_th  [(size_t)BB*NQ*CI];
__device__ __align__(256) __half d_ph  [(size_t)BB*NKp*CI];
__device__ __align__(256) __half d_g2  [(size_t)BB*CI*NKp];
__device__ __align__(256) __half d_f   [(size_t)BB*NQ*NKp];   // exp(logits)
__device__ __align__(256) __half d_y   [(size_t)BB*NQ*CI];
__device__ __align__(256) __half d_wy  [(size_t)BB*CC*NQ];
__device__ __align__(256) __half d_thw [CI*CC];
__device__ __align__(256) __half d_phw [CI*CC];
__device__ __align__(256) __half d_gw  [CI*CC];
__device__ __align__(256) __half d_ww  [CC*CI];
__device__ float d_rowsum[(size_t)BB*NQ];
__device__ float d_bnsum[CC];
__device__ float d_bnsq [CC];
__device__ float d_mean[CC];
__device__ float d_istd[CC];

// ---------------- helpers ----------------
__device__ __forceinline__ uint32_t s2u(const void* p) {
    uint32_t a;
    asm("{ .reg .u64 t; cvta.to.shared.u64 t, %1; cvt.u32.u64 %0, t; }" : "=r"(a) : "l"(p));
    return a;
}
__device__ __forceinline__ void st2h(__half* p, float a, float b) {
    *(__half2*)p = __floats2half2_rn(a, b);
}

// ---------------- fp16 mma.sync TN GEMM core ----------------
// CTA 128x128, warp 64x32, BK=64, NSTAGE=3, 2 CTAs/SM.
// D[M,N] = scale * A[M,K] @ B[N,K]^T (+ biasM[m]) (+ biasN[n])
// rowSum : D = exp2(val) (cols<nValid else 0), row sums -> rowSum[m]
// rowRcp : D = val / rowRcp[m]
// bnSum/bnSq : per-row sum/sumsq accumulation
// Output staged through smem -> fully coalesced 16B stores.
#define ROW_B  144
#define TILE_B (128*ROW_B)
#define STG_B  (2*TILE_B)
#define NSTAGE 3
#define GEMM_SMEM (NSTAGE*STG_B)       // 110592 -> 2 CTAs/SM
#define EPI_ROW 144                    // halfs per staged row (128 + 16 pad)

__device__ __forceinline__ void gemm_dev(
    const __half* __restrict__ A, const __half* __restrict__ B,
    __half* __restrict__ D, int K, int lda, int ldb, int ldd,
    long long sA, long long sB, long long sD,
    const float* __restrict__ biasM, const float* __restrict__ biasN,
    float scale,
    float* __restrict__ rowSum, const float* __restrict__ rowRcp,
    int nValid, long long sR,
    float* __restrict__ bnSum, float* __restrict__ bnSq,
    int bx, int by, int bz)
{
    extern __shared__ char smem[];
    __shared__ float sm_r1[128];
    __shared__ float sm_r2[128];
    const uint32_t smem_b = s2u(smem);
    const int tid = threadIdx.x, wid = tid >> 5, lane = tid & 31;
    const int wm = wid >> 2, wn = wid & 3;
    const int g = lane >> 2, tg = lane & 3;
    const int m0 = by << 7, n0 = bx << 7;
    A += (long long)bz * sA + (size_t)m0 * lda;
    B += (long long)bz * sB + (size_t)n0 * ldb;
    D += (long long)bz * sD;
    if (rowSum) rowSum += (long long)bz * sR;
    if (rowRcp) rowRcp += (long long)bz * sR;
    const int ktiles = K >> 6;

    const int prow[4] = { (tid + 0) >> 3, (tid + 256) >> 3, (tid + 512) >> 3, (tid + 768) >> 3 };
    const int pc = tid & 7;

    const uint32_t aoff = (uint32_t)(wm * 64 + (lane & 15)) * ROW_B + ((lane >> 4) << 4);
    const uint32_t boff = (uint32_t)TILE_B
                        + (uint32_t)(wn * 32 + ((lane >> 4) << 3) + (lane & 7)) * ROW_B
                        + (((lane >> 3) & 1) << 4);

    float acc[4][4][4];
    #pragma unroll
    for (int i = 0; i < 4; i++)
        #pragma unroll
        for (int j = 0; j < 4; j++)
            #pragma unroll
            for (int q = 0; q < 4; q++) acc[i][j][q] = 0.0f;

    #pragma unroll
    for (int s = 0; s < NSTAGE - 1; s++) {
        const __half* Ab = A + (s << 6) + (pc << 3);
        const __half* Bb = B + (s << 6) + (pc << 3);
        uint32_t Sa = smem_b + s * STG_B + pc * 16;
        uint32_t Sb = Sa + TILE_B;
        #pragma unroll
        for (int l = 0; l < 4; l++) {
            asm volatile("cp.async.cg.shared.global [%0], [%1], 16;"
                         :: "r"(Sa + prow[l] * ROW_B), "l"(Ab + (size_t)prow[l] * lda));
            asm volatile("cp.async.cg.shared.global [%0], [%1], 16;"
                         :: "r"(Sb + prow[l] * ROW_B), "l"(Bb + (size_t)prow[l] * ldb));
        }
        asm volatile("cp.async.commit_group;");
    }

    int sc = 0;
    for (int kt = 0; kt < ktiles; kt++) {
        asm volatile("cp.async.wait_group %0;" :: "n"(NSTAGE - 2));
        __syncthreads();

        const int pf = kt + NSTAGE - 1;
        if (pf < ktiles) {
            int sp = sc + NSTAGE - 1; if (sp >= NSTAGE) sp -= NSTAGE;
            const __half* Ab = A + (pf << 6) + (pc << 3);
            const __half* Bb = B + (pf << 6) + (pc << 3);
            uint32_t Sa = smem_b + sp * STG_B + pc * 16;
            uint32_t Sb = Sa + TILE_B;
            #pragma unroll
            for (int l = 0; l < 4; l++) {
                asm volatile("cp.async.cg.shared.global [%0], [%1], 16;"
                             :: "r"(Sa + prow[l] * ROW_B), "l"(Ab + (size_t)prow[l] * lda));
                asm volatile("cp.async.cg.shared.global [%0], [%1], 16;"
                             :: "r"(Sb + prow[l] * ROW_B), "l"(Bb + (size_t)prow[l] * ldb));
            }
        }
        asm volatile("cp.async.commit_group;");

        const uint32_t sbase = smem_b + sc * STG_B;
        const uint32_t aB = sbase + aoff;
        const uint32_t bB = sbase + boff;

        #pragma unroll
        for (int ks = 0; ks < 4; ks++) {
            const uint32_t kb = ks * 32;
            uint32_t a[4][4], b[4][2];
            #pragma unroll
            for (int mt = 0; mt < 4; mt++)
                asm volatile("ldmatrix.sync.aligned.m8n8.x4.shared.b16 {%0,%1,%2,%3}, [%4];"
                             : "=r"(a[mt][0]), "=r"(a[mt][1]), "=r"(a[mt][2]), "=r"(a[mt][3])
                             : "r"(aB + mt * (16 * ROW_B) + kb));
            asm volatile("ldmatrix.sync.aligned.m8n8.x4.shared.b16 {%0,%1,%2,%3}, [%4];"
                         : "=r"(b[0][0]), "=r"(b[0][1]), "=r"(b[1][0]), "=r"(b[1][1])
                         : "r"(bB + kb));
            asm volatile("ldmatrix.sync.aligned.m8n8.x4.shared.b16 {%0,%1,%2,%3}, [%4];"
                         : "=r"(b[2][0]), "=r"(b[2][1]), "=r"(b[3][0]), "=r"(b[3][1])
                         : "r"(bB + 16 * ROW_B + kb));
            #pragma unroll
            for (int mt = 0; mt < 4; mt++)
                #pragma unroll
                for (int nt = 0; nt < 4; nt++)
                    asm("mma.sync.aligned.m16n8k16.row.col.f32.f16.f16.f32 "
                        "{%0,%1,%2,%3}, {%4,%5,%6,%7}, {%8,%9}, {%0,%1,%2,%3};"
                        : "+f"(acc[mt][nt][0]), "+f"(acc[mt][nt][1]),
                          "+f"(acc[mt][nt][2]), "+f"(acc[mt][nt][3])
                        : "r"(a[mt][0]), "r"(a[mt][1]), "r"(a[mt][2]), "r"(a[mt][3]),
                          "r"(b[nt][0]), "r"(b[nt][1]));
        }
        if (++sc == NSTAGE) sc = 0;
    }

    // ---------------- epilogue: math -> smem stage -> coalesced stores -----
    const bool doStats = (rowSum != nullptr) || (bnSum != nullptr);
    __syncthreads();                        // pipeline stages now reusable
    __half* stage = (__half*)smem;          // 128 x EPI_ROW halfs (36.8 KB)
    if (doStats) {
        if (tid < 128) { sm_r1[tid] = 0.0f; sm_r2[tid] = 0.0f; }
        __syncthreads();
    }
    #pragma unroll
    for (int mt = 0; mt < 4; mt++) {
        const int rl = wm * 64 + mt * 16 + g;          // local row
        const int r0 = m0 + rl;
        const float bm0 = biasM ? biasM[r0] : 0.0f;
        const float bm1 = biasM ? biasM[r0 + 8] : 0.0f;
        const float rs0 = rowRcp ? __frcp_rn(rowRcp[r0]) : 1.0f;
        const float rs1 = rowRcp ? __frcp_rn(rowRcp[r0 + 8]) : 1.0f;
        float s0 = 0.0f, s1 = 0.0f, q0 = 0.0f, q1 = 0.0f;
        #pragma unroll
        for (int nt = 0; nt < 4; nt++) {
            const int cl = wn * 32 + nt * 8 + tg * 2;  // local col
            const int col = n0 + cl;
            const float bn0 = biasN ? biasN[col] : 0.0f;
            const float bn1 = biasN ? biasN[col + 1] : 0.0f;
            float v0 = acc[mt][nt][0] * scale + bm0 + bn0;
            float v1 = acc[mt][nt][1] * scale + bm0 + bn1;
            float v2 = acc[mt][nt][2] * scale + bm1 + bn0;
            float v3 = acc[mt][nt][3] * scale + bm1 + bn1;
            if (rowSum) {
                // scale already includes log2(e): exp(x) == exp2(x*log2e)
                v0 = (col     < nValid) ? exp2f(v0) : 0.0f;
                v1 = (col + 1 < nValid) ? exp2f(v1) : 0.0f;
                v2 = (col     < nValid) ? exp2f(v2) : 0.0f;
                v3 = (col + 1 < nValid) ? exp2f(v3) : 0.0f;
                s0 += v0 + v1; s1 += v2 + v3;
            }
            if (bnSum) {
                s0 += v0 + v1; s1 += v2 + v3;
                q0 += v0 * v0 + v1 * v1; q1 += v2 * v2 + v3 * v3;
            }
            v0 *= rs0; v1 *= rs0; v2 *= rs1; v3 *= rs1;
            st2h(stage + (size_t)rl * EPI_ROW + cl, v0, v1);
            st2h(stage + (size_t)(rl + 8) * EPI_ROW + cl, v2, v3);
        }
        if (doStats) {
            s0 += __shfl_xor_sync(0xffffffffu, s0, 1);
            s0 += __shfl_xor_sync(0xffffffffu, s0, 2);
            s1 += __shfl_xor_sync(0xffffffffu, s1, 1);
            s1 += __shfl_xor_sync(0xffffffffu, s1, 2);
            if (bnSum) {
                q0 += __shfl_xor_sync(0xffffffffu, q0, 1);
                q0 += __shfl_xor_sync(0xffffffffu, q0, 2);
                q1 += __shfl_xor_sync(0xffffffffu, q1, 1);
                q1 += __shfl_xor_sync(0xffffffffu, q1, 2);
            }
            if (tg == 0) {
                atomicAdd(&sm_r1[rl], s0);
                atomicAdd(&sm_r1[rl + 8], s1);
                if (bnSum) {
                    atomicAdd(&sm_r2[rl], q0);
                    atomicAdd(&sm_r2[rl + 8], q1);
                }
            }
        }
    }
    __syncthreads();
    if (doStats && tid < 128) {
        if (rowSum) atomicAdd(&rowSum[m0 + tid], sm_r1[tid]);
        if (bnSum) {
            atomicAdd(&bnSum[m0 + tid], sm_r1[tid]);
            atomicAdd(&bnSq[m0 + tid],  sm_r2[tid]);
        }
    }
    // coalesced copy: 2048 x 16B chunks, 8 per thread
    #pragma unroll
    for (int l = 0; l < 8; l++) {
        const int id = tid + l * 256;
        const int row = id >> 4, c8 = id & 15;
        float4 v = *(const float4*)(stage + (size_t)row * EPI_ROW + c8 * 8);
        *(float4*)(D + (size_t)(m0 + row) * ldd + n0 + c8 * 8) = v;
    }
}

// Standard single-GEMM launcher
__global__ __launch_bounds__(256, 2)
void gemm_tn(const __half* __restrict__ A, const __half* __restrict__ B,
             __half* __restrict__ D, int K, int lda, int ldb, int ldd,
             long long sA, long long sB, long long sD,
             const float* __restrict__ biasM, const float* __restrict__ biasN,
             float scale,
             float* __restrict__ rowSum, const float* __restrict__ rowRcp,
             int nValid, long long sR,
             float* __restrict__ bnSum, float* __restrict__ bnSq)
{
    gemm_dev(A, B, D, K, lda, ldb, ldd, sA, sB, sD, biasM, biasN, scale,
             rowSum, rowRcp, nValid, sR, bnSum, bnSq,
             blockIdx.x, blockIdx.y, blockIdx.z);
}

// Merged theta+phi+g2 projections: one flat grid, tails pack.
#define PROJ3_GRID 2368
__global__ __launch_bounds__(256, 2)
void proj3_kernel(const float* __restrict__ theta_b,
                  const float* __restrict__ phi_b,
                  const float* __restrict__ g_b)
{
    const int t = blockIdx.x;
    const __half *A, *B;
    __half* D;
    int ldd, bx, by, bz;
    long long sA, sB, sD;
    const float *bM, *bN;
    if (t < 1568) {
        int r = t; bz = r / 392; r -= bz * 392; by = r >> 2; bx = r & 3;
        A = d_xt; B = d_thw; D = d_th; ldd = CI;
        sA = (long long)NQ * CC; sB = 0; sD = (long long)NQ * CI;
        bM = nullptr; bN = theta_b;
    } else if (t < 1968) {
        int r = t - 1568; bz = r / 100; r -= bz * 100; by = r >> 2; bx = r & 3;
        A = d_xpt; B = d_phw; D = d_ph; ldd = CI;
        sA = (long long)NKp * CC; sB = 0; sD = (long long)NKp * CI;
        bM = nullptr; bN = phi_b;
    } else {
        int r = t - 1968; bz = r / 100; r -= bz * 100; by = r / 25; bx = r - by * 25;
        A = d_gw; B = d_xpt; D = d_g2; ldd = NKp;
        sA = 0; sB = (long long)NKp * CC; sD = (long long)CI * NKp;
        bM = g_b; bN = nullptr;
    }
    gemm_dev(A, B, D, CC, CC, CC, ldd, sA, sB, sD, bM, bN, 1.0f,
             nullptr, nullptr, 0, 0LL, nullptr, nullptr, bx, by, bz);
}

// ---------------- fp32 -> fp16 weights + zero accumulators ----------------
__global__ void f2h4_kernel(const float* __restrict__ w0, const float* __restrict__ w1,
                            const float* __restrict__ w2, const float* __restrict__ w3)
{
    const int WSZ2 = CI * CC / 2;
    int i = blockIdx.x * 256 + threadIdx.x;
    int seg = i / WSZ2, off = i - seg * WSZ2;
    const float* s = (seg == 0) ? w0 : (seg == 1) ? w1 : (seg == 2) ? w2 : w3;
    __half* d = (seg == 0) ? d_thw : (seg == 1) ? d_phw : (seg == 2) ? d_gw : d_ww;
    float2 v = *(const float2*)(s + 2 * off);
    *(__half2*)(d + 2 * off) = __floats2half2_rn(v.x, v.y);
    if (i < BB * NQ) d_rowsum[i] = 0.0f;
    if (i < CC) { d_bnsum[i] = 0.0f; d_bnsq[i] = 0.0f; }
}

// ---------------- BN finalize ----------------
__global__ void bn_finalize_kernel()
{
    int c = blockIdx.x * 256 + threadIdx.x;
    if (c >= CC) return;
    const float cnt = (float)((long long)BB * NQ);
    float mean = d_bnsum[c] / cnt;
    float var = d_bnsq[c] / cnt - mean * mean;
    d_mean[c] = mean;
    d_istd[c] = rsqrtf(var + BN_EPS);
}

// ---------------- transpose x (B,C,NQ) -> xt fp16 (B,NQ,C) ----------------
__global__ void transpose_x(const float* __restrict__ x)
{
    __shared__ float t[32][33];
    const int b = blockIdx.z;
    const int n0 = blockIdx.x << 5, c0 = blockIdx.y << 5;
    const int tx = threadIdx.x, ty = threadIdx.y;
    const float* xp = x + (size_t)b * CC * NQ;
    __half* xo = d_xt + (size_t)b * NQ * CC;
    #pragma unroll
    for (int i = 0; i < 4; i++)
        t[ty + i*8][tx] = xp[(size_t)(c0 + ty + i*8) * NQ + n0 + tx];
    __syncthreads();
    #pragma unroll
    for (int i = 0; i < 4; i++)
        xo[(size_t)(n0 + ty + i*8) * CC + c0 + tx] = __float2half(t[tx][ty + i*8]);
}

// ---------------- pool xt -> xpt fp16 (B,NKp,C), pad rows zero -------------
__global__ void pool_kernel()
{
    const int b = blockIdx.y, nk = blockIdx.x;
    __half2* o = (__half2*)(d_xpt + ((size_t)b * NKp + nk) * CC);
    if (nk >= NKr) {
        for (int c = threadIdx.x; c < CC/2; c += 256) o[c] = __half2half2(__float2half(0.0f));
        return;
    }
    const int wi = nk % 14, hi = (nk / 14) % 14, t = nk / 196;
    const __half2* r0 = (const __half2*)(d_xt + ((size_t)b * NQ + (size_t)(t * HH + 2 * hi) * WW + 2 * wi) * CC);
    const int s1 = CC/2, s2 = WW*CC/2, s3 = (WW+1)*CC/2;
    for (int c = threadIdx.x; c < CC/2; c += 256)
        o[c] = __hmax2(__hmax2(r0[c], r0[s1 + c]), __hmax2(r0[s2 + c], r0[s3 + c]));
}

// ---------------- BN apply + residual (4 elems/thread) ----------------
__global__ void bn_apply_kernel(const float* __restrict__ x,
                                const float* __restrict__ gamma,
                                const float* __restrict__ beta,
                                float* __restrict__ out)
{
    size_t i = (size_t)blockIdx.x * 256 + threadIdx.x;   // quad index
    if (i >= (size_t)BB * CC * NQ / 4) return;
    int c = (int)((i / (NQ/4)) % CC);
    uint2 wraw = *(const uint2*)(d_wy + 4 * i);
    float2 wa = __half22float2(*(__half2*)&wraw.x);
    float2 wb = __half22float2(*(__half2*)&wraw.y);
    float4 xv = *(const float4*)(x + 4 * i);
    const float a = d_istd[c] * gamma[c];
    const float m = d_mean[c], bt = beta[c];
    float4 r;
    r.x = (wa.x - m) * a + bt + xv.x;
    r.y = (wa.y - m) * a + bt + xv.y;
    r.z = (wb.x - m) * a + bt + xv.z;
    r.w = (wb.y - m) * a + bt + xv.w;
    *(float4*)(out + 4 * i) = r;
}

// ---------------- host ----------------
extern "C" void kernel_launch(void* const* d_in, const int* in_sizes, int n_in,
                              void* d_out, int out_size)
{
    (void)in_sizes; (void)n_in; (void)out_size;
    const float* x       = (const float*)d_in[0];
    const float* theta_w = (const float*)d_in[1];
    const float* theta_b = (const float*)d_in[2];
    const float* phi_w   = (const float*)d_in[3];
    const float* phi_b   = (const float*)d_in[4];
    const float* g_w     = (const float*)d_in[5];
    const float* g_b     = (const float*)d_in[6];
    const float* w_w     = (const float*)d_in[7];
    const float* w_b     = (const float*)d_in[8];
    const float* bn_g    = (const float*)d_in[9];
    const float* bn_b    = (const float*)d_in[10];
    float* out = (float*)d_out;

    cudaFuncSetAttribute(gemm_tn, cudaFuncAttributeMaxDynamicSharedMemorySize, GEMM_SMEM);
    cudaFuncSetAttribute(proj3_kernel, cudaFuncAttributeMaxDynamicSharedMemorySize, GEMM_SMEM);

    void *p_th, *p_ph, *p_g2, *p_f, *p_y, *p_wy, *p_ww, *p_rs, *p_bs, *p_bq;
    cudaGetSymbolAddress(&p_th, d_th);
    cudaGetSymbolAddress(&p_ph, d_ph);
    cudaGetSymbolAddress(&p_g2, d_g2);
    cudaGetSymbolAddress(&p_f, d_f);
    cudaGetSymbolAddress(&p_y, d_y);
    cudaGetSymbolAddress(&p_wy, d_wy);
    cudaGetSymbolAddress(&p_ww, d_ww);
    cudaGetSymbolAddress(&p_rs, d_rowsum);
    cudaGetSymbolAddress(&p_bs, d_bnsum);
    cudaGetSymbolAddress(&p_bq, d_bnsq);

    const float fscale2 = 1.442695040888963f / sqrtf((float)CI);  // log2e folded

    f2h4_kernel<<<4 * CI * CC / 512, 256>>>(theta_w, phi_w, g_w, w_w);
    transpose_x<<<dim3(NQ/32, CC/32, BB), dim3(32,8)>>>(x);
    pool_kernel<<<dim3(NKp, BB), 256>>>();

    // theta + phi + g2 in one packed launch
    proj3_kernel<<<PROJ3_GRID, 256, GEMM_SMEM>>>(theta_b, phi_b, g_b);

    // f (B,NQ,NKp) = exp(theta @ phi^T * scale), pad cols zero, rowsums
    gemm_tn<<<dim3(NKp/128, NQ/128, BB), 256, GEMM_SMEM>>>(
        (const __half*)p_th, (const __half*)p_ph, (__half*)p_f,
        CI, CI, CI, NKp, (long long)NQ*CI, (long long)NKp*CI, (long long)NQ*NKp,
        nullptr, nullptr, fscale2, (float*)p_rs, nullptr, NKr, (long long)NQ,
        nullptr, nullptr);

    // y (B,NQ,CI) = (expf @ g2^T) / rowsum[m]
    gemm_tn<<<dim3(CI/128, NQ/128, BB), 256, GEMM_SMEM>>>(
        (const __half*)p_f, (const __half*)p_g2, (__half*)p_y,
        NKp, NKp, NKp, CI, (long long)NQ*NKp, (long long)CI*NKp, (long long)NQ*CI,
        nullptr, nullptr, 1.0f, nullptr, (const float*)p_rs, 0, (long long)NQ,
        nullptr, nullptr);
    // wy (B,CC,NQ) = w_w @ y^T + w_b[m], fused BN sum/sumsq
    gemm_tn<<<dim3(NQ/128, CC/128, BB), 256, GEMM_SMEM>>>(
        (const __half*)p_ww, (const __half*)p_y, (__half*)p_wy,
        CI, CI, CI, NQ, 0LL, (long long)NQ*CI, (long long)CC*NQ,
        w_b, nullptr, 1.0f, nullptr, nullptr, 0, 0LL,
        (float*)p_bs, (float*)p_bq);

    bn_finalize_kernel<<<(CC + 255)/256, 256>>>();
    {
        size_t tot = (size_t)BB * CC * NQ / 4;
        bn_apply_kernel<<<(unsigned)((tot + 255) / 256), 256>>>(x, bn_g, bn_b, out);
    }
}

// round 16
// speedup vs baseline: 1.2423x; 1.0117x over previous
#include <cuda_runtime.h>
#include <cuda_fp16.h>
#include <math.h>
#include <stdint.h>

#define BB 4
#define CC 1024
#define CI 512
#define TT 16
#define HH 28
#define WW 28
#define NQ 12544
#define NKr 3136
#define NKp 3200
#define BN_EPS 1e-5f

// ---------------- scratch ----------------
__device__ __align__(256) __half d_xt  [(size_t)BB*NQ*CC];
__device__ __align__(256) __half d_xpt [(size_t)BB*NKp*CC];
__device__ __align__(256) __half d_th  [(size_t)BB*NQ*CI];
__device__ __align__(256) __half d_ph  [(size_t)BB*NKp*CI];
__device__ __align__(256) __half d_g2  [(size_t)BB*CI*NKp];
__device__ __align__(256) __half d_f   [(size_t)BB*NQ*NKp];   // exp(logits)
__device__ __align__(256) __half d_y   [(size_t)BB*NQ*CI];
__device__ __align__(256) __half d_wy  [(size_t)BB*CC*NQ];
__device__ __align__(256) __half d_thw [CI*CC];
__device__ __align__(256) __half d_phw [CI*CC];
__device__ __align__(256) __half d_gw  [CI*CC];
__device__ __align__(256) __half d_ww  [CC*CI];
__device__ float d_rowsum[(size_t)BB*NQ];
__device__ float d_bnsum[CC];
__device__ float d_bnsq [CC];
__device__ float d_mean[CC];
__device__ float d_istd[CC];

// ---------------- helpers ----------------
__device__ __forceinline__ uint32_t s2u(const void* p) {
    uint32_t a;
    asm("{ .reg .u64 t; cvta.to.shared.u64 t, %1; cvt.u32.u64 %0, t; }" : "=r"(a) : "l"(p));
    return a;
}
__device__ __forceinline__ void st2h(__half* p, float a, float b) {
    *(__half2*)p = __floats2half2_rn(a, b);
}
// exp2 of a packed pair via one MUFU op
__device__ __forceinline__ uint32_t h2exp2(float a, float b) {
    uint32_t h;
    asm("cvt.rn.f16x2.f32 %0, %1, %2;" : "=r"(h) : "f"(b), "f"(a));  // lo=a, hi=b
    asm("ex2.approx.f16x2 %0, %0;" : "+r"(h));
    return h;
}

// ---------------- fp16 mma.sync TN GEMM core ----------------
// CTA 128x128, warp 64x32, BK=64, NSTAGE=3, 2 CTAs/SM.
// D[M,N] = scale * A[M,K] @ B[N,K]^T (+ biasM[m]) (+ biasN[n])
// rowSum : D = exp2(val) (cols<nValid else 0), row sums -> rowSum[m]
// rowRcp : D = val / rowRcp[m]
// bnSum/bnSq : per-row sum/sumsq accumulation
// Output staged through smem -> fully coalesced 16B stores.
#define ROW_B  144
#define TILE_B (128*ROW_B)
#define STG_B  (2*TILE_B)
#define NSTAGE 3
#define GEMM_SMEM (NSTAGE*STG_B)       // 110592 -> 2 CTAs/SM
#define EPI_ROW 144

__device__ __forceinline__ void gemm_dev(
    const __half* __restrict__ A, const __half* __restrict__ B,
    __half* __restrict__ D, int K, int lda, int ldb, int ldd,
    long long sA, long long sB, long long sD,
    const float* __restrict__ biasM, const float* __restrict__ biasN,
    float scale,
    float* __restrict__ rowSum, const float* __restrict__ rowRcp,
    int nValid, long long sR,
    float* __restrict__ bnSum, float* __restrict__ bnSq,
    int bx, int by, int bz)
{
    extern __shared__ char smem[];
    __shared__ float sm_r1[128];
    __shared__ float sm_r2[128];
    const uint32_t smem_b = s2u(smem);
    const int tid = threadIdx.x, wid = tid >> 5, lane = tid & 31;
    const int wm = wid >> 2, wn = wid & 3;
    const int g = lane >> 2, tg = lane & 3;
    const int m0 = by << 7, n0 = bx << 7;
    A += (long long)bz * sA + (size_t)m0 * lda;
    B += (long long)bz * sB + (size_t)n0 * ldb;
    D += (long long)bz * sD;
    if (rowSum) rowSum += (long long)bz * sR;
    if (rowRcp) rowRcp += (long long)bz * sR;
    const int ktiles = K >> 6;

    const int prow[4] = { (tid + 0) >> 3, (tid + 256) >> 3, (tid + 512) >> 3, (tid + 768) >> 3 };
    const int pc = tid & 7;

    const uint32_t aoff = (uint32_t)(wm * 64 + (lane & 15)) * ROW_B + ((lane >> 4) << 4);
    const uint32_t boff = (uint32_t)TILE_B
                        + (uint32_t)(wn * 32 + ((lane >> 4) << 3) + (lane & 7)) * ROW_B
                        + (((lane >> 3) & 1) << 4);

    float acc[4][4][4];
    #pragma unroll
    for (int i = 0; i < 4; i++)
        #pragma unroll
        for (int j = 0; j < 4; j++)
            #pragma unroll
            for (int q = 0; q < 4; q++) acc[i][j][q] = 0.0f;

    #pragma unroll
    for (int s = 0; s < NSTAGE - 1; s++) {
        const __half* Ab = A + (s << 6) + (pc << 3);
        const __half* Bb = B + (s << 6) + (pc << 3);
        uint32_t Sa = smem_b + s * STG_B + pc * 16;
        uint32_t Sb = Sa + TILE_B;
        #pragma unroll
        for (int l = 0; l < 4; l++) {
            asm volatile("cp.async.cg.shared.global [%0], [%1], 16;"
                         :: "r"(Sa + prow[l] * ROW_B), "l"(Ab + (size_t)prow[l] * lda));
            asm volatile("cp.async.cg.shared.global [%0], [%1], 16;"
                         :: "r"(Sb + prow[l] * ROW_B), "l"(Bb + (size_t)prow[l] * ldb));
        }
        asm volatile("cp.async.commit_group;");
    }

    int sc = 0;
    for (int kt = 0; kt < ktiles; kt++) {
        asm volatile("cp.async.wait_group %0;" :: "n"(NSTAGE - 2));
        __syncthreads();

        const int pf = kt + NSTAGE - 1;
        if (pf < ktiles) {
            int sp = sc + NSTAGE - 1; if (sp >= NSTAGE) sp -= NSTAGE;
            const __half* Ab = A + (pf << 6) + (pc << 3);
            const __half* Bb = B + (pf << 6) + (pc << 3);
            uint32_t Sa = smem_b + sp * STG_B + pc * 16;
            uint32_t Sb = Sa + TILE_B;
            #pragma unroll
            for (int l = 0; l < 4; l++) {
                asm volatile("cp.async.cg.shared.global [%0], [%1], 16;"
                             :: "r"(Sa + prow[l] * ROW_B), "l"(Ab + (size_t)prow[l] * lda));
                asm volatile("cp.async.cg.shared.global [%0], [%1], 16;"
                             :: "r"(Sb + prow[l] * ROW_B), "l"(Bb + (size_t)prow[l] * ldb));
            }
        }
        asm volatile("cp.async.commit_group;");

        const uint32_t sbase = smem_b + sc * STG_B;
        const uint32_t aB = sbase + aoff;
        const uint32_t bB = sbase + boff;

        #pragma unroll
        for (int ks = 0; ks < 4; ks++) {
            const uint32_t kb = ks * 32;
            uint32_t a[4][4], b[4][2];
            #pragma unroll
            for (int mt = 0; mt < 4; mt++)
                asm volatile("ldmatrix.sync.aligned.m8n8.x4.shared.b16 {%0,%1,%2,%3}, [%4];"
                             : "=r"(a[mt][0]), "=r"(a[mt][1]), "=r"(a[mt][2]), "=r"(a[mt][3])
                             : "r"(aB + mt * (16 * ROW_B) + kb));
            asm volatile("ldmatrix.sync.aligned.m8n8.x4.shared.b16 {%0,%1,%2,%3}, [%4];"
                         : "=r"(b[0][0]), "=r"(b[0][1]), "=r"(b[1][0]), "=r"(b[1][1])
                         : "r"(bB + kb));
            asm volatile("ldmatrix.sync.aligned.m8n8.x4.shared.b16 {%0,%1,%2,%3}, [%4];"
                         : "=r"(b[2][0]), "=r"(b[2][1]), "=r"(b[3][0]), "=r"(b[3][1])
                         : "r"(bB + 16 * ROW_B + kb));
            #pragma unroll
            for (int mt = 0; mt < 4; mt++)
                #pragma unroll
                for (int nt = 0; nt < 4; nt++)
                    asm("mma.sync.aligned.m16n8k16.row.col.f32.f16.f16.f32 "
                        "{%0,%1,%2,%3}, {%4,%5,%6,%7}, {%8,%9}, {%0,%1,%2,%3};"
                        : "+f"(acc[mt][nt][0]), "+f"(acc[mt][nt][1]),
                          "+f"(acc[mt][nt][2]), "+f"(acc[mt][nt][3])
                        : "r"(a[mt][0]), "r"(a[mt][1]), "r"(a[mt][2]), "r"(a[mt][3]),
                          "r"(b[nt][0]), "r"(b[nt][1]));
        }
        if (++sc == NSTAGE) sc = 0;
    }

    // ---------------- epilogue: math -> smem stage -> coalesced stores -----
    const bool doStats = (rowSum != nullptr) || (bnSum != nullptr);
    __syncthreads();
    __half* stage = (__half*)smem;
    if (doStats) {
        if (tid < 128) { sm_r1[tid] = 0.0f; sm_r2[tid] = 0.0f; }
        __syncthreads();
    }
    #pragma unroll
    for (int mt = 0; mt < 4; mt++) {
        const int rl = wm * 64 + mt * 16 + g;
        const int r0 = m0 + rl;
        const float bm0 = biasM ? biasM[r0] : 0.0f;
        const float bm1 = biasM ? biasM[r0 + 8] : 0.0f;
        const float rs0 = rowRcp ? __frcp_rn(rowRcp[r0]) : 1.0f;
        const float rs1 = rowRcp ? __frcp_rn(rowRcp[r0 + 8]) : 1.0f;
        float s0 = 0.0f, s1 = 0.0f, q0 = 0.0f, q1 = 0.0f;
        #pragma unroll
        for (int nt = 0; nt < 4; nt++) {
            const int cl = wn * 32 + nt * 8 + tg * 2;
            const int col = n0 + cl;
            const float bn0 = biasN ? biasN[col] : 0.0f;
            const float bn1 = biasN ? biasN[col + 1] : 0.0f;
            float v0 = acc[mt][nt][0] * scale + bm0 + bn0;
            float v1 = acc[mt][nt][1] * scale + bm0 + bn1;
            float v2 = acc[mt][nt][2] * scale + bm1 + bn0;
            float v3 = acc[mt][nt][3] * scale + bm1 + bn1;
            if (rowSum) {
                // exp2 pairs in fp16 (scale already includes log2e).
                // NKr is even: a pair never straddles the valid boundary.
                uint32_t h0 = (col < nValid) ? h2exp2(v0, v1) : 0u;
                uint32_t h2 = (col < nValid) ? h2exp2(v2, v3) : 0u;
                float2 f0 = __half22float2(*(__half2*)&h0);
                float2 f2 = __half22float2(*(__half2*)&h2);
                s0 += f0.x + f0.y; s1 += f2.x + f2.y;
                *(uint32_t*)(stage + (size_t)rl * EPI_ROW + cl) = h0;
                *(uint32_t*)(stage + (size_t)(rl + 8) * EPI_ROW + cl) = h2;
            } else {
                if (bnSum) {
                    s0 += v0 + v1; s1 += v2 + v3;
                    q0 += v0 * v0 + v1 * v1; q1 += v2 * v2 + v3 * v3;
                }
                v0 *= rs0; v1 *= rs0; v2 *= rs1; v3 *= rs1;
                st2h(stage + (size_t)rl * EPI_ROW + cl, v0, v1);
                st2h(stage + (size_t)(rl + 8) * EPI_ROW + cl, v2, v3);
            }
        }
        if (doStats) {
            s0 += __shfl_xor_sync(0xffffffffu, s0, 1);
            s0 += __shfl_xor_sync(0xffffffffu, s0, 2);
            s1 += __shfl_xor_sync(0xffffffffu, s1, 1);
            s1 += __shfl_xor_sync(0xffffffffu, s1, 2);
            if (bnSum) {
                q0 += __shfl_xor_sync(0xffffffffu, q0, 1);
                q0 += __shfl_xor_sync(0xffffffffu, q0, 2);
                q1 += __shfl_xor_sync(0xffffffffu, q1, 1);
                q1 += __shfl_xor_sync(0xffffffffu, q1, 2);
            }
            if (tg == 0) {
                atomicAdd(&sm_r1[rl], s0);
                atomicAdd(&sm_r1[rl + 8], s1);
                if (bnSum) {
                    atomicAdd(&sm_r2[rl], q0);
                    atomicAdd(&sm_r2[rl + 8], q1);
                }
            }
        }
    }
    __syncthreads();
    if (doStats && tid < 128) {
        if (rowSum) atomicAdd(&rowSum[m0 + tid], sm_r1[tid]);
        if (bnSum) {
            atomicAdd(&bnSum[m0 + tid], sm_r1[tid]);
            atomicAdd(&bnSq[m0 + tid],  sm_r2[tid]);
        }
    }
    // coalesced copy: 2048 x 16B chunks, 8 per thread
    #pragma unroll
    for (int l = 0; l < 8; l++) {
        const int id = tid + l * 256;
        const int row = id >> 4, c8 = id & 15;
        float4 v = *(const float4*)(stage + (size_t)row * EPI_ROW + c8 * 8);
        *(float4*)(D + (size_t)(m0 + row) * ldd + n0 + c8 * 8) = v;
    }
}

// Standard single-GEMM launcher
__global__ __launch_bounds__(256, 2)
void gemm_tn(const __half* __restrict__ A, const __half* __restrict__ B,
             __half* __restrict__ D, int K, int lda, int ldb, int ldd,
             long long sA, long long sB, long long sD,
             const float* __restrict__ biasM, const float* __restrict__ biasN,
             float scale,
             float* __restrict__ rowSum, const float* __restrict__ rowRcp,
             int nValid, long long sR,
             float* __restrict__ bnSum, float* __restrict__ bnSq)
{
    gemm_dev(A, B, D, K, lda, ldb, ldd, sA, sB, sD, biasM, biasN, scale,
             rowSum, rowRcp, nValid, sR, bnSum, bnSq,
             blockIdx.x, blockIdx.y, blockIdx.z);
}

// Merged theta+phi+g2 projections: one flat grid, tails pack.
#define PROJ3_GRID 2368
__global__ __launch_bounds__(256, 2)
void proj3_kernel(const float* __restrict__ theta_b,
                  const float* __restrict__ phi_b,
                  const float* __restrict__ g_b)
{
    const int t = blockIdx.x;
    const __half *A, *B;
    __half* D;
    int ldd, bx, by, bz;
    long long sA, sB, sD;
    const float *bM, *bN;
    if (t < 1568) {
        int r = t; bz = r / 392; r -= bz * 392; by = r >> 2; bx = r & 3;
        A = d_xt; B = d_thw; D = d_th; ldd = CI;
        sA = (long long)NQ * CC; sB = 0; sD = (long long)NQ * CI;
        bM = nullptr; bN = theta_b;
    } else if (t < 1968) {
        int r = t - 1568; bz = r / 100; r -= bz * 100; by = r >> 2; bx = r & 3;
        A = d_xpt; B = d_phw; D = d_ph; ldd = CI;
        sA = (long long)NKp * CC; sB = 0; sD = (long long)NKp * CI;
        bM = nullptr; bN = phi_b;
    } else {
        int r = t - 1968; bz = r / 100; r -= bz * 100; by = r / 25; bx = r - by * 25;
        A = d_gw; B = d_xpt; D = d_g2; ldd = NKp;
        sA = 0; sB = (long long)NKp * CC; sD = (long long)CI * NKp;
        bM = g_b; bN = nullptr;
    }
    gemm_dev(A, B, D, CC, CC, CC, ldd, sA, sB, sD, bM, bN, 1.0f,
             nullptr, nullptr, 0, 0LL, nullptr, nullptr, bx, by, bz);
}

// ---------------- fp32 -> fp16 weights + zero accumulators ----------------
__global__ void f2h4_kernel(const float* __restrict__ w0, const float* __restrict__ w1,
                            const float* __restrict__ w2, const float* __restrict__ w3)
{
    const int WSZ2 = CI * CC / 2;
    int i = blockIdx.x * 256 + threadIdx.x;
    int seg = i / WSZ2, off = i - seg * WSZ2;
    const float* s = (seg == 0) ? w0 : (seg == 1) ? w1 : (seg == 2) ? w2 : w3;
    __half* d = (seg == 0) ? d_thw : (seg == 1) ? d_phw : (seg == 2) ? d_gw : d_ww;
    float2 v = *(const float2*)(s + 2 * off);
    *(__half2*)(d + 2 * off) = __floats2half2_rn(v.x, v.y);
    if (i < BB * NQ) d_rowsum[i] = 0.0f;
    if (i < CC) { d_bnsum[i] = 0.0f; d_bnsq[i] = 0.0f; }
}

// ---------------- BN finalize ----------------
__global__ void bn_finalize_kernel()
{
    int c = blockIdx.x * 256 + threadIdx.x;
    if (c >= CC) return;
    const float cnt = (float)((long long)BB * NQ);
    float mean = d_bnsum[c] / cnt;
    float var = d_bnsq[c] / cnt - mean * mean;
    d_mean[c] = mean;
    d_istd[c] = rsqrtf(var + BN_EPS);
}

// ---------------- transpose x (B,C,NQ) -> xt fp16 (B,NQ,C) ----------------
__global__ void transpose_x(const float* __restrict__ x)
{
    __shared__ float t[32][33];
    const int b = blockIdx.z;
    const int n0 = blockIdx.x << 5, c0 = blockIdx.y << 5;
    const int tx = threadIdx.x, ty = threadIdx.y;
    const float* xp = x + (size_t)b * CC * NQ;
    __half* xo = d_xt + (size_t)b * NQ * CC;
    #pragma unroll
    for (int i = 0; i < 4; i++)
        t[ty + i*8][tx] = xp[(size_t)(c0 + ty + i*8) * NQ + n0 + tx];
    __syncthreads();
    #pragma unroll
    for (int i = 0; i < 4; i++)
        xo[(size_t)(n0 + ty + i*8) * CC + c0 + tx] = __float2half(t[tx][ty + i*8]);
}

// ---------------- pool xt -> xpt fp16 (B,NKp,C), pad rows zero -------------
__global__ void pool_kernel()
{
    const int b = blockIdx.y, nk = blockIdx.x;
    __half2* o = (__half2*)(d_xpt + ((size_t)b * NKp + nk) * CC);
    if (nk >= NKr) {
        for (int c = threadIdx.x; c < CC/2; c += 256) o[c] = __half2half2(__float2half(0.0f));
        return;
    }
    const int wi = nk % 14, hi = (nk / 14) % 14, t = nk / 196;
    const __half2* r0 = (const __half2*)(d_xt + ((size_t)b * NQ + (size_t)(t * HH + 2 * hi) * WW + 2 * wi) * CC);
    const int s1 = CC/2, s2 = WW*CC/2, s3 = (WW+1)*CC/2;
    for (int c = threadIdx.x; c < CC/2; c += 256)
        o[c] = __hmax2(__hmax2(r0[c], r0[s1 + c]), __hmax2(r0[s2 + c], r0[s3 + c]));
}

// ---------------- BN apply + residual (4 elems/thread) ----------------
__global__ void bn_apply_kernel(const float* __restrict__ x,
                                const float* __restrict__ gamma,
                                const float* __restrict__ beta,
                                float* __restrict__ out)
{
    size_t i = (size_t)blockIdx.x * 256 + threadIdx.x;
    if (i >= (size_t)BB * CC * NQ / 4) return;
    int c = (int)((i / (NQ/4)) % CC);
    uint2 wraw = *(const uint2*)(d_wy + 4 * i);
    float2 wa = __half22float2(*(__half2*)&wraw.x);
    float2 wb = __half22float2(*(__half2*)&wraw.y);
    float4 xv = *(const float4*)(x + 4 * i);
    const float a = d_istd[c] * gamma[c];
    const float m = d_mean[c], bt = beta[c];
    float4 r;
    r.x = (wa.x - m) * a + bt + xv.x;
    r.y = (wa.y - m) * a + bt + xv.y;
    r.z = (wb.x - m) * a + bt + xv.z;
    r.w = (wb.y - m) * a + bt + xv.w;
    *(float4*)(out + 4 * i) = r;
}

// ---------------- host ----------------
extern "C" void kernel_launch(void* const* d_in, const int* in_sizes, int n_in,
                              void* d_out, int out_size)
{
    (void)in_sizes; (void)n_in; (void)out_size;
    const float* x       = (const float*)d_in[0];
    const float* theta_w = (const float*)d_in[1];
    const float* theta_b = (const float*)d_in[2];
    const float* phi_w   = (const float*)d_in[3];
    const float* phi_b   = (const float*)d_in[4];
    const float* g_w     = (const float*)d_in[5];
    const float* g_b     = (const float*)d_in[6];
    const float* w_w     = (const float*)d_in[7];
    const float* w_b     = (const float*)d_in[8];
    const float* bn_g    = (const float*)d_in[9];
    const float* bn_b    = (const float*)d_in[10];
    float* out = (float*)d_out;

    cudaFuncSetAttribute(gemm_tn, cudaFuncAttributeMaxDynamicSharedMemorySize, GEMM_SMEM);
    cudaFuncSetAttribute(proj3_kernel, cudaFuncAttributeMaxDynamicSharedMemorySize, GEMM_SMEM);

    void *p_th, *p_ph, *p_g2, *p_f, *p_y, *p_wy, *p_ww, *p_rs, *p_bs, *p_bq;
    cudaGetSymbolAddress(&p_th, d_th);
    cudaGetSymbolAddress(&p_ph, d_ph);
    cudaGetSymbolAddress(&p_g2, d_g2);
    cudaGetSymbolAddress(&p_f, d_f);
    cudaGetSymbolAddress(&p_y, d_y);
    cudaGetSymbolAddress(&p_wy, d_wy);
    cudaGetSymbolAddress(&p_ww, d_ww);
    cudaGetSymbolAddress(&p_rs, d_rowsum);
    cudaGetSymbolAddress(&p_bs, d_bnsum);
    cudaGetSymbolAddress(&p_bq, d_bnsq);

    const float fscale2 = 1.442695040888963f / sqrtf((float)CI);  // log2e folded

    f2h4_kernel<<<4 * CI * CC / 512, 256>>>(theta_w, phi_w, g_w, w_w);
    transpose_x<<<dim3(NQ/32, CC/32, BB), dim3(32,8)>>>(x);
    pool_kernel<<<dim3(NKp, BB), 256>>>();

    // theta + phi + g2 in one packed launch
    proj3_kernel<<<PROJ3_GRID, 256, GEMM_SMEM>>>(theta_b, phi_b, g_b);

    // f (B,NQ,NKp) = exp(theta @ phi^T * scale), pad cols zero, rowsums
    gemm_tn<<<dim3(NKp/128, NQ/128, BB), 256, GEMM_SMEM>>>(
        (const __half*)p_th, (const __half*)p_ph, (__half*)p_f,
        CI, CI, CI, NKp, (long long)NQ*CI, (long long)NKp*CI, (long long)NQ*NKp,
        nullptr, nullptr, fscale2, (float*)p_rs, nullptr, NKr, (long long)NQ,
        nullptr, nullptr);

    // y (B,NQ,CI) = (expf @ g2^T) / rowsum[m]
    gemm_tn<<<dim3(CI/128, NQ/128, BB), 256, GEMM_SMEM>>>(
        (const __half*)p_f, (const __half*)p_g2, (__half*)p_y,
        NKp, NKp, NKp, CI, (long long)NQ*NKp, (long long)CI*NKp, (long long)NQ*CI,
        nullptr, nullptr, 1.0f, nullptr, (const float*)p_rs, 0, (long long)NQ,
        nullptr, nullptr);
    // wy (B,CC,NQ) = w_w @ y^T + w_b[m], fused BN sum/sumsq
    gemm_tn<<<dim3(NQ/128, CC/128, BB), 256, GEMM_SMEM>>>(
        (const __half*)p_ww, (const __half*)p_y, (__half*)p_wy,
        CI, CI, CI, NQ, 0LL, (long long)NQ*CI, (long long)CC*NQ,
        w_b, nullptr, 1.0f, nullptr, nullptr, 0, 0LL,
        (float*)p_bs, (float*)p_bq);

    bn_finalize_kernel<<<(CC + 255)/256, 256>>>();
    {
        size_t tot = (size_t)BB * CC * NQ / 4;
        bn_apply_kernel<<<(unsigned)((tot + 255) / 256), 256>>>(x, bn_g, bn_b, out);
    }
}